// round 2
// baseline (speedup 1.0000x reference)
#include <cuda_runtime.h>
#include <math.h>

#define NFEAT   256
#define HIDDEN  256
#define PCH     64
#define NCLASS  4
#define MAXN    100000
#define MAXE    1600000

// ---------------- device scratch ----------------
__device__ int   g_is64;
__device__ float g_CW[HIDDEN * NFEAT];
__device__ float g_cb[HIDDEN];
__device__ float g_proj[MAXN * 8];          // [pa0..3, pb0..3] per node
__device__ float g_c[(size_t)MAXN * HIDDEN];
__device__ int   g_counts[MAXN];
__device__ int   g_rowstart[MAXN];
__device__ int   g_cursor[MAXN];
__device__ int   g_csrcol[MAXE];

// ---------------- index width sniffing ----------------
__global__ void k_detect(const unsigned int* __restrict__ rowp, int E) {
    if (threadIdx.x == 0 && blockIdx.x == 0) {
        int n = E < 64 ? E : 64;
        int all_hi_zero = 1;
        for (int i = 0; i < n; i++)
            if (rowp[2 * i + 1] != 0u) { all_hi_zero = 0; break; }
        g_is64 = all_hi_zero;
    }
}

// ---------------- fold conv into lin ----------------
__global__ void k_fold(const float* __restrict__ conv_W,
                       const float* __restrict__ lin_W,
                       const float* __restrict__ lin_b) {
    int t = blockIdx.x, f = threadIdx.x;
    int k = t >> 6, q = t & 63;
    const float* cw = conv_W + (k * PCH + q) * PCH;
    const float* lw = lin_W + (size_t)k * PCH * NFEAT;
    float s = 0.f;
    #pragma unroll 8
    for (int p = 0; p < PCH; p++) s = fmaf(cw[p], lw[p * NFEAT + f], s);
    g_CW[t * NFEAT + f] = s;
    if (f == 0) {
        const float* lb = lin_b + k * PCH;
        float b = 0.f;
        for (int p = 0; p < PCH; p++) b = fmaf(cw[p], lb[p], b);
        g_cb[t] = b;
    }
}

// ---------------- per-node assignment projections ----------------
__global__ void k_proj(const float* __restrict__ x,
                       const float* __restrict__ asg_W1, int N) {
    int warp = (blockIdx.x * blockDim.x + threadIdx.x) >> 5;
    int lane = threadIdx.x & 31;
    if (warp >= N) return;
    const float* xr = x + (size_t)warp * NFEAT;
    float pa[4] = {0,0,0,0}, pb[4] = {0,0,0,0};
    #pragma unroll
    for (int t = 0; t < 8; t++) {
        int f = lane + 32 * t;
        float xv = xr[f];
        #pragma unroll
        for (int c = 0; c < 4; c++) {
            pa[c] = fmaf(xv, asg_W1[c * 512 + f], pa[c]);
            pb[c] = fmaf(xv, asg_W1[c * 512 + 256 + f], pb[c]);
        }
    }
    #pragma unroll
    for (int c = 0; c < 4; c++)
        #pragma unroll
        for (int o = 16; o > 0; o >>= 1) {
            pa[c] += __shfl_xor_sync(0xFFFFFFFFu, pa[c], o);
            pb[c] += __shfl_xor_sync(0xFFFFFFFFu, pb[c], o);
        }
    if (lane == 0) {
        #pragma unroll
        for (int c = 0; c < 4; c++) {
            g_proj[warp * 8 + c]     = pa[c];
            g_proj[warp * 8 + 4 + c] = pb[c];
        }
    }
}

// ---------------- c = X @ CW^T + cb ----------------
#define BM 128
#define BN 128
#define BK 8
__global__ __launch_bounds__(256, 2)
void k_cgemm(const float* __restrict__ X, int N) {
    __shared__ float As[BK][BM + 4];
    __shared__ float Bs[BK][BN + 4];
    int m0 = blockIdx.x * BM, n0 = blockIdx.y * BN;
    int tid = threadIdx.x;
    int ty = tid >> 4, tx = tid & 15;
    int lm = tid >> 1, lf = (tid & 1) * 4;

    float acc[8][8];
    #pragma unroll
    for (int i = 0; i < 8; i++)
        #pragma unroll
        for (int j = 0; j < 8; j++) acc[i][j] = 0.f;

    for (int k0 = 0; k0 < NFEAT; k0 += BK) {
        float4 av;
        int gm = m0 + lm;
        if (gm < N) av = *(const float4*)(X + (size_t)gm * NFEAT + k0 + lf);
        else        av = make_float4(0.f,0.f,0.f,0.f);
        As[lf+0][lm] = av.x; As[lf+1][lm] = av.y;
        As[lf+2][lm] = av.z; As[lf+3][lm] = av.w;
        float4 bv = *(const float4*)(g_CW + (n0 + lm) * NFEAT + k0 + lf);
        Bs[lf+0][lm] = bv.x; Bs[lf+1][lm] = bv.y;
        Bs[lf+2][lm] = bv.z; Bs[lf+3][lm] = bv.w;
        __syncthreads();
        #pragma unroll
        for (int kk = 0; kk < BK; kk++) {
            float a[8], b[8];
            *(float4*)&a[0] = *(const float4*)&As[kk][ty * 8];
            *(float4*)&a[4] = *(const float4*)&As[kk][ty * 8 + 4];
            *(float4*)&b[0] = *(const float4*)&Bs[kk][tx * 8];
            *(float4*)&b[4] = *(const float4*)&Bs[kk][tx * 8 + 4];
            #pragma unroll
            for (int i = 0; i < 8; i++)
                #pragma unroll
                for (int j = 0; j < 8; j++)
                    acc[i][j] = fmaf(a[i], b[j], acc[i][j]);
        }
        __syncthreads();
    }
    #pragma unroll
    for (int i = 0; i < 8; i++) {
        int gm = m0 + ty * 8 + i;
        if (gm >= N) break;
        float* outp = g_c + (size_t)gm * HIDDEN + n0 + tx * 8;
        #pragma unroll
        for (int j = 0; j < 8; j += 4) {
            float4 v;
            v.x = acc[i][j+0] + g_cb[n0 + tx*8 + j+0];
            v.y = acc[i][j+1] + g_cb[n0 + tx*8 + j+1];
            v.z = acc[i][j+2] + g_cb[n0 + tx*8 + j+2];
            v.w = acc[i][j+3] + g_cb[n0 + tx*8 + j+3];
            *(float4*)(outp + j) = v;
        }
    }
}

// ---------------- CSR build ----------------
__global__ void k_zero(int N) {
    int i = blockIdx.x * blockDim.x + threadIdx.x;
    if (i < N) g_counts[i] = 0;
}

__global__ void k_hist(const void* __restrict__ rowp, int E) {
    int e = blockIdx.x * blockDim.x + threadIdx.x;
    if (e >= E) return;
    int r = g_is64 ? (int)((const long long*)rowp)[e] : ((const int*)rowp)[e];
    atomicAdd(&g_counts[r], 1);
}

__global__ void k_scan(int N) {
    __shared__ int sh[1024];
    int tid = threadIdx.x;
    int chunk = (N + 1023) >> 10;
    int lo = tid * chunk;
    int hi = lo + chunk; if (hi > N) hi = N; if (lo > N) lo = N;
    int s = 0;
    for (int i = lo; i < hi; i++) s += g_counts[i];
    sh[tid] = s;
    __syncthreads();
    int v = s;
    for (int o = 1; o < 1024; o <<= 1) {
        int u = (tid >= o) ? sh[tid - o] : 0;
        __syncthreads();
        v += u;
        sh[tid] = v;
        __syncthreads();
    }
    int run = v - s;
    for (int i = lo; i < hi; i++) {
        g_rowstart[i] = run;
        g_cursor[i]   = run;
        run += g_counts[i];
    }
}

__global__ void k_scatter(const void* __restrict__ rowp,
                          const void* __restrict__ colp, int E) {
    int e = blockIdx.x * blockDim.x + threadIdx.x;
    if (e >= E) return;
    int r, c;
    if (g_is64) {
        r = (int)((const long long*)rowp)[e];
        c = (int)((const long long*)colp)[e];
    } else {
        r = ((const int*)rowp)[e];
        c = ((const int*)colp)[e];
    }
    int pos = atomicAdd(&g_cursor[r], 1);
    g_csrcol[pos] = c;
}

// ---------------- fused aggregate + bias + norm + classifier ----------------
// one warp per row; message accumulated in registers, no atomics
__global__ __launch_bounds__(256)
void k_agg(const float* __restrict__ asg_b1, const float* __restrict__ asg_W2,
           const float* __restrict__ asg_b2, const float* __restrict__ bias,
           const float* __restrict__ cls_W, const float* __restrict__ cls_b,
           float* __restrict__ hout, float* __restrict__ logits, int N) {
    int r    = (blockIdx.x * blockDim.x + threadIdx.x) >> 5;
    int lane = threadIdx.x & 31;
    if (r >= N) return;

    float b1[4], b2[4], W2[16];
    #pragma unroll
    for (int k = 0; k < 4; k++) { b1[k] = __ldg(asg_b1 + k); b2[k] = __ldg(asg_b2 + k); }
    #pragma unroll
    for (int k = 0; k < 16; k++) W2[k] = __ldg(asg_W2 + k);

    // row's pb (broadcast load)
    float4 pbv = *(const float4*)(g_proj + r * 8 + 4);
    float pb[4] = {pbv.x, pbv.y, pbv.z, pbv.w};

    int start = g_rowstart[r];
    int deg   = g_counts[r];

    float acc[8];
    #pragma unroll
    for (int t = 0; t < 8; t++) acc[t] = 0.f;

    for (int base = 0; base < deg; base += 32) {
        int cnt = deg - base; if (cnt > 32) cnt = 32;
        // each lane computes softmax weights for one edge of this batch
        int   mycol = 0;
        float w0 = 0, w1 = 0, w2 = 0, w3 = 0;
        if (lane < cnt) {
            mycol = g_csrcol[start + base + lane];
            float4 pav = __ldg((const float4*)(g_proj + (size_t)mycol * 8));
            float h1[4] = {pav.x + pb[0] + b1[0], pav.y + pb[1] + b1[1],
                           pav.z + pb[2] + b1[2], pav.w + pb[3] + b1[3]};
            float h2[4], mx = -1e30f;
            #pragma unroll
            for (int k = 0; k < 4; k++) {
                float s = b2[k];
                #pragma unroll
                for (int d = 0; d < 4; d++) s = fmaf(h1[d], W2[k*4+d], s);
                h2[k] = s; mx = fmaxf(mx, s);
            }
            float e0 = __expf(h2[0]-mx), e1 = __expf(h2[1]-mx);
            float e2 = __expf(h2[2]-mx), e3 = __expf(h2[3]-mx);
            float inv = 1.f / (e0+e1+e2+e3);
            w0 = e0*inv; w1 = e1*inv; w2 = e2*inv; w3 = e3*inv;
        }
        // broadcast each edge; all lanes accumulate its 256-vector
        for (int j = 0; j < cnt; j++) {
            int   cj  = __shfl_sync(0xFFFFFFFFu, mycol, j);
            float wj0 = __shfl_sync(0xFFFFFFFFu, w0, j);
            float wj1 = __shfl_sync(0xFFFFFFFFu, w1, j);
            float wj2 = __shfl_sync(0xFFFFFFFFu, w2, j);
            float wj3 = __shfl_sync(0xFFFFFFFFu, w3, j);
            const float* cr = g_c + (size_t)cj * HIDDEN;
            float wj[4] = {wj0, wj1, wj2, wj3};
            #pragma unroll
            for (int t = 0; t < 8; t++)
                acc[t] = fmaf(__ldg(cr + lane + 32 * t), wj[t >> 1], acc[t]);
        }
    }

    // bias + per-group L2 norm
    float ss[4] = {0,0,0,0};
    #pragma unroll
    for (int t = 0; t < 8; t++) {
        acc[t] += __ldg(bias + lane + 32 * t);
        ss[t >> 1] = fmaf(acc[t], acc[t], ss[t >> 1]);
    }
    #pragma unroll
    for (int k = 0; k < 4; k++)
        #pragma unroll
        for (int o = 16; o > 0; o >>= 1)
            ss[k] += __shfl_xor_sync(0xFFFFFFFFu, ss[k], o);
    float invn[4];
    #pragma unroll
    for (int k = 0; k < 4; k++)
        invn[k] = 1.f / fmaxf(sqrtf(ss[k]), 1e-12f);

    float* hr = hout + (size_t)r * HIDDEN;
    float lp[4] = {0,0,0,0};
    #pragma unroll
    for (int t = 0; t < 8; t++) {
        float v = acc[t] * invn[t >> 1];
        int j = lane + 32 * t;
        hr[j] = v;
        #pragma unroll
        for (int cc = 0; cc < 4; cc++)
            lp[cc] = fmaf(v, __ldg(cls_W + cc * HIDDEN + j), lp[cc]);
    }
    #pragma unroll
    for (int cc = 0; cc < 4; cc++)
        #pragma unroll
        for (int o = 16; o > 0; o >>= 1)
            lp[cc] += __shfl_xor_sync(0xFFFFFFFFu, lp[cc], o);
    if (lane == 0) {
        #pragma unroll
        for (int cc = 0; cc < 4; cc++)
            logits[(size_t)r * NCLASS + cc] = lp[cc] + __ldg(cls_b + cc);
    }
}

// ---------------- launch ----------------
extern "C" void kernel_launch(void* const* d_in, const int* in_sizes, int n_in,
                              void* d_out, int out_size) {
    const float* x      = (const float*)d_in[0];
    const void*  rowp   = d_in[1];
    const void*  colp   = d_in[2];
    const float* asg_W1 = (const float*)d_in[3];
    const float* asg_b1 = (const float*)d_in[4];
    const float* asg_W2 = (const float*)d_in[5];
    const float* asg_b2 = (const float*)d_in[6];
    const float* lin_W  = (const float*)d_in[7];
    const float* lin_b  = (const float*)d_in[8];
    const float* conv_W = (const float*)d_in[9];
    const float* bias   = (const float*)d_in[10];
    const float* cls_W  = (const float*)d_in[11];
    const float* cls_b  = (const float*)d_in[12];

    int N = in_sizes[0] / NFEAT;
    int E = in_sizes[1];

    float* hout   = (float*)d_out;
    float* logits = hout + (size_t)N * HIDDEN;

    k_detect<<<1, 32>>>((const unsigned int*)rowp, E);
    k_fold<<<HIDDEN, NFEAT>>>(conv_W, lin_W, lin_b);
    k_proj<<<(N + 7) / 8, 256>>>(x, asg_W1, N);
    dim3 gg((N + BM - 1) / BM, HIDDEN / BN);
    k_cgemm<<<gg, 256>>>(x, N);
    k_zero<<<(N + 255) / 256, 256>>>(N);
    k_hist<<<(E + 255) / 256, 256>>>(rowp, E);
    k_scan<<<1, 1024>>>(N);
    k_scatter<<<(E + 255) / 256, 256>>>(rowp, colp, E);
    k_agg<<<(N + 7) / 8, 256>>>(asg_b1, asg_W2, asg_b2, bias,
                                cls_W, cls_b, hout, logits, N);
}

// round 4
// speedup vs baseline: 1.0601x; 1.0601x over previous
#include <cuda_runtime.h>
#include <math.h>

#define NFEAT   256
#define HIDDEN  256
#define PCH     64
#define NCLASS  4
#define MAXN    100000
#define MAXE    1600000

// ---------------- device scratch ----------------
__device__ int   g_is64;
__device__ float g_CW[HIDDEN * NFEAT];
__device__ float g_cb[HIDDEN];
__device__ float g_proj[MAXN * 8];          // [pa0..3, pb0..3] per node
__device__ float g_c[(size_t)MAXN * HIDDEN];
__device__ int   g_counts[MAXN];
__device__ int   g_rowstart[MAXN];
__device__ int   g_cursor[MAXN];
__device__ int   g_csrcol[MAXE];

// ---------------- index width sniffing ----------------
__global__ void k_detect(const unsigned int* __restrict__ rowp, int E) {
    if (threadIdx.x == 0 && blockIdx.x == 0) {
        int n = E < 64 ? E : 64;
        int all_hi_zero = 1;
        for (int i = 0; i < n; i++)
            if (rowp[2 * i + 1] != 0u) { all_hi_zero = 0; break; }
        g_is64 = all_hi_zero;
    }
}

// ---------------- fold conv into lin ----------------
__global__ void k_fold(const float* __restrict__ conv_W,
                       const float* __restrict__ lin_W,
                       const float* __restrict__ lin_b) {
    int t = blockIdx.x, f = threadIdx.x;
    int k = t >> 6, q = t & 63;
    const float* cw = conv_W + (k * PCH + q) * PCH;
    const float* lw = lin_W + (size_t)k * PCH * NFEAT;
    float s = 0.f;
    #pragma unroll 8
    for (int p = 0; p < PCH; p++) s = fmaf(cw[p], lw[p * NFEAT + f], s);
    g_CW[t * NFEAT + f] = s;
    if (f == 0) {
        const float* lb = lin_b + k * PCH;
        float b = 0.f;
        for (int p = 0; p < PCH; p++) b = fmaf(cw[p], lb[p], b);
        g_cb[t] = b;
    }
}

// ---------------- per-node assignment projections ----------------
__global__ void k_proj(const float* __restrict__ x,
                       const float* __restrict__ asg_W1, int N) {
    int warp = (blockIdx.x * blockDim.x + threadIdx.x) >> 5;
    int lane = threadIdx.x & 31;
    if (warp >= N) return;
    const float* xr = x + (size_t)warp * NFEAT;
    float pa[4] = {0,0,0,0}, pb[4] = {0,0,0,0};
    #pragma unroll
    for (int t = 0; t < 8; t++) {
        int f = lane + 32 * t;
        float xv = xr[f];
        #pragma unroll
        for (int c = 0; c < 4; c++) {
            pa[c] = fmaf(xv, asg_W1[c * 512 + f], pa[c]);
            pb[c] = fmaf(xv, asg_W1[c * 512 + 256 + f], pb[c]);
        }
    }
    #pragma unroll
    for (int c = 0; c < 4; c++)
        #pragma unroll
        for (int o = 16; o > 0; o >>= 1) {
            pa[c] += __shfl_xor_sync(0xFFFFFFFFu, pa[c], o);
            pb[c] += __shfl_xor_sync(0xFFFFFFFFu, pb[c], o);
        }
    if (lane == 0) {
        #pragma unroll
        for (int c = 0; c < 4; c++) {
            g_proj[warp * 8 + c]     = pa[c];
            g_proj[warp * 8 + 4 + c] = pb[c];
        }
    }
}

// ---------------- c = X @ CW^T + cb  (double-buffered) ----------------
#define BM 128
#define BN 128
#define BK 8
__global__ __launch_bounds__(256, 2)
void k_cgemm(const float* __restrict__ X, int N) {
    __shared__ float As[2][BK][BM + 4];
    __shared__ float Bs[2][BK][BN + 4];
    int m0 = blockIdx.x * BM, n0 = blockIdx.y * BN;
    int tid = threadIdx.x;
    int ty = tid >> 4, tx = tid & 15;
    int lm = tid >> 1, lf = (tid & 1) * 4;
    int gm = m0 + lm;

    float acc[8][8];
    #pragma unroll
    for (int i = 0; i < 8; i++)
        #pragma unroll
        for (int j = 0; j < 8; j++) acc[i][j] = 0.f;

    // preload tile 0
    {
        float4 av = (gm < N) ? *(const float4*)(X + (size_t)gm * NFEAT + lf)
                             : make_float4(0.f,0.f,0.f,0.f);
        As[0][lf+0][lm] = av.x; As[0][lf+1][lm] = av.y;
        As[0][lf+2][lm] = av.z; As[0][lf+3][lm] = av.w;
        float4 bv = *(const float4*)(g_CW + (n0 + lm) * NFEAT + lf);
        Bs[0][lf+0][lm] = bv.x; Bs[0][lf+1][lm] = bv.y;
        Bs[0][lf+2][lm] = bv.z; Bs[0][lf+3][lm] = bv.w;
    }
    __syncthreads();

    int p = 0;
    for (int k0 = 0; k0 < NFEAT; k0 += BK) {
        float4 av, bv;
        bool pref = (k0 + BK < NFEAT);
        if (pref) {
            av = (gm < N) ? *(const float4*)(X + (size_t)gm * NFEAT + k0 + BK + lf)
                          : make_float4(0.f,0.f,0.f,0.f);
            bv = *(const float4*)(g_CW + (n0 + lm) * NFEAT + k0 + BK + lf);
        }
        #pragma unroll
        for (int kk = 0; kk < BK; kk++) {
            float a[8], b[8];
            *(float4*)&a[0] = *(const float4*)&As[p][kk][ty * 8];
            *(float4*)&a[4] = *(const float4*)&As[p][kk][ty * 8 + 4];
            *(float4*)&b[0] = *(const float4*)&Bs[p][kk][tx * 8];
            *(float4*)&b[4] = *(const float4*)&Bs[p][kk][tx * 8 + 4];
            #pragma unroll
            for (int i = 0; i < 8; i++)
                #pragma unroll
                for (int j = 0; j < 8; j++)
                    acc[i][j] = fmaf(a[i], b[j], acc[i][j]);
        }
        if (pref) {
            int q = p ^ 1;
            As[q][lf+0][lm] = av.x; As[q][lf+1][lm] = av.y;
            As[q][lf+2][lm] = av.z; As[q][lf+3][lm] = av.w;
            Bs[q][lf+0][lm] = bv.x; Bs[q][lf+1][lm] = bv.y;
            Bs[q][lf+2][lm] = bv.z; Bs[q][lf+3][lm] = bv.w;
        }
        __syncthreads();
        p ^= 1;
    }

    #pragma unroll
    for (int i = 0; i < 8; i++) {
        int om = m0 + ty * 8 + i;
        if (om >= N) break;
        float* outp = g_c + (size_t)om * HIDDEN + n0 + tx * 8;
        #pragma unroll
        for (int j = 0; j < 8; j += 4) {
            float4 v;
            v.x = acc[i][j+0] + g_cb[n0 + tx*8 + j+0];
            v.y = acc[i][j+1] + g_cb[n0 + tx*8 + j+1];
            v.z = acc[i][j+2] + g_cb[n0 + tx*8 + j+2];
            v.w = acc[i][j+3] + g_cb[n0 + tx*8 + j+3];
            *(float4*)(outp + j) = v;
        }
    }
}

// ---------------- CSR build ----------------
__global__ void k_zero(int N) {
    int i = blockIdx.x * blockDim.x + threadIdx.x;
    if (i < N) g_counts[i] = 0;
}

__global__ void k_hist(const void* __restrict__ rowp, int E) {
    int e = blockIdx.x * blockDim.x + threadIdx.x;
    if (e >= E) return;
    int r = g_is64 ? (int)((const long long*)rowp)[e] : ((const int*)rowp)[e];
    atomicAdd(&g_counts[r], 1);
}

__global__ void k_scan(int N) {
    __shared__ int sh[1024];
    int tid = threadIdx.x;
    int chunk = (N + 1023) >> 10;
    int lo = tid * chunk;
    int hi = lo + chunk; if (hi > N) hi = N; if (lo > N) lo = N;
    int s = 0;
    for (int i = lo; i < hi; i++) s += g_counts[i];
    sh[tid] = s;
    __syncthreads();
    int v = s;
    for (int o = 1; o < 1024; o <<= 1) {
        int u = (tid >= o) ? sh[tid - o] : 0;
        __syncthreads();
        v += u;
        sh[tid] = v;
        __syncthreads();
    }
    int run = v - s;
    for (int i = lo; i < hi; i++) {
        g_rowstart[i] = run;
        g_cursor[i]   = run;
        run += g_counts[i];
    }
}

__global__ void k_scatter(const void* __restrict__ rowp,
                          const void* __restrict__ colp, int E) {
    int e = blockIdx.x * blockDim.x + threadIdx.x;
    if (e >= E) return;
    int r, c;
    if (g_is64) {
        r = (int)((const long long*)rowp)[e];
        c = (int)((const long long*)colp)[e];
    } else {
        r = ((const int*)rowp)[e];
        c = ((const int*)colp)[e];
    }
    int pos = atomicAdd(&g_cursor[r], 1);
    g_csrcol[pos] = c;
}

// ---------------- fused aggregate + bias + norm + classifier ----------------
// one warp per row; lane owns columns [lane*8, lane*8+8) -> single group
// per edge: 1 smem weight read + 2 LDG.128 + 8 FMA, independent across edges
__global__ __launch_bounds__(256)
void k_agg(const float* __restrict__ asg_b1, const float* __restrict__ asg_W2,
           const float* __restrict__ asg_b2, const float* __restrict__ bias,
           const float* __restrict__ cls_W, const float* __restrict__ cls_b,
           float* __restrict__ hout, float* __restrict__ logits, int N) {
    __shared__ float sw[8][32][4];   // weights per warp/edge/group
    __shared__ int   sc[8][32];      // col per warp/edge

    int wid  = threadIdx.x >> 5;
    int lane = threadIdx.x & 31;
    int r    = blockIdx.x * 8 + wid;
    if (r >= N) return;

    float b1[4], b2[4], W2[16];
    #pragma unroll
    for (int k = 0; k < 4; k++) { b1[k] = __ldg(asg_b1 + k); b2[k] = __ldg(asg_b2 + k); }
    #pragma unroll
    for (int k = 0; k < 16; k++) W2[k] = __ldg(asg_W2 + k);

    float4 pbv = *(const float4*)(g_proj + r * 8 + 4);
    float pb[4] = {pbv.x, pbv.y, pbv.z, pbv.w};

    int start = g_rowstart[r];
    int deg   = g_counts[r];
    int myg   = lane >> 3;           // group of this lane's 8 columns

    float4 acc0 = make_float4(0.f,0.f,0.f,0.f);
    float4 acc1 = make_float4(0.f,0.f,0.f,0.f);

    for (int base = 0; base < deg; base += 32) {
        int cnt = deg - base; if (cnt > 32) cnt = 32;
        float w0 = 0.f, w1 = 0.f, w2 = 0.f, w3 = 0.f;
        int   mycol = 0;
        if (lane < cnt) {
            mycol = g_csrcol[start + base + lane];
            float4 pav = __ldg((const float4*)(g_proj + (size_t)mycol * 8));
            float h1[4] = {pav.x + pb[0] + b1[0], pav.y + pb[1] + b1[1],
                           pav.z + pb[2] + b1[2], pav.w + pb[3] + b1[3]};
            float h2[4], mx = -1e30f;
            #pragma unroll
            for (int k = 0; k < 4; k++) {
                float s = b2[k];
                #pragma unroll
                for (int d = 0; d < 4; d++) s = fmaf(h1[d], W2[k*4+d], s);
                h2[k] = s; mx = fmaxf(mx, s);
            }
            float e0 = __expf(h2[0]-mx), e1 = __expf(h2[1]-mx);
            float e2 = __expf(h2[2]-mx), e3 = __expf(h2[3]-mx);
            float inv = 1.f / (e0+e1+e2+e3);
            w0 = e0*inv; w1 = e1*inv; w2 = e2*inv; w3 = e3*inv;
        }
        sw[wid][lane][0] = w0; sw[wid][lane][1] = w1;
        sw[wid][lane][2] = w2; sw[wid][lane][3] = w3;
        sc[wid][lane] = mycol;
        __syncwarp();

        #pragma unroll 4
        for (int j = 0; j < cnt; j++) {
            int   cj = sc[wid][j];
            float wj = sw[wid][j][myg];
            const float4* cr = (const float4*)(g_c + (size_t)cj * HIDDEN) + lane * 2;
            float4 v0 = __ldg(cr);
            float4 v1 = __ldg(cr + 1);
            acc0.x = fmaf(v0.x, wj, acc0.x); acc0.y = fmaf(v0.y, wj, acc0.y);
            acc0.z = fmaf(v0.z, wj, acc0.z); acc0.w = fmaf(v0.w, wj, acc0.w);
            acc1.x = fmaf(v1.x, wj, acc1.x); acc1.y = fmaf(v1.y, wj, acc1.y);
            acc1.z = fmaf(v1.z, wj, acc1.z); acc1.w = fmaf(v1.w, wj, acc1.w);
        }
        __syncwarp();
    }

    // bias + per-group L2 norm (each lane's 8 cols all in group myg)
    float4 bb0 = __ldg((const float4*)bias + lane * 2);
    float4 bb1 = __ldg((const float4*)bias + lane * 2 + 1);
    acc0.x += bb0.x; acc0.y += bb0.y; acc0.z += bb0.z; acc0.w += bb0.w;
    acc1.x += bb1.x; acc1.y += bb1.y; acc1.z += bb1.z; acc1.w += bb1.w;

    float ss = acc0.x*acc0.x + acc0.y*acc0.y + acc0.z*acc0.z + acc0.w*acc0.w
             + acc1.x*acc1.x + acc1.y*acc1.y + acc1.z*acc1.z + acc1.w*acc1.w;
    #pragma unroll
    for (int o = 1; o < 8; o <<= 1)
        ss += __shfl_xor_sync(0xFFFFFFFFu, ss, o);   // reduce within 8-lane group
    float invn = 1.f / fmaxf(sqrtf(ss), 1e-12f);

    acc0.x *= invn; acc0.y *= invn; acc0.z *= invn; acc0.w *= invn;
    acc1.x *= invn; acc1.y *= invn; acc1.z *= invn; acc1.w *= invn;

    float4* hr = (float4*)(hout + (size_t)r * HIDDEN) + lane * 2;
    hr[0] = acc0;
    hr[1] = acc1;

    float lp[4];
    #pragma unroll
    for (int cc = 0; cc < 4; cc++) {
        const float4* cwp = (const float4*)(cls_W + cc * HIDDEN) + lane * 2;
        float4 c0 = __ldg(cwp), c1 = __ldg(cwp + 1);
        lp[cc] = acc0.x*c0.x + acc0.y*c0.y + acc0.z*c0.z + acc0.w*c0.w
               + acc1.x*c1.x + acc1.y*c1.y + acc1.z*c1.z + acc1.w*c1.w;
    }
    #pragma unroll
    for (int cc = 0; cc < 4; cc++)
        #pragma unroll
        for (int o = 16; o > 0; o >>= 1)
            lp[cc] += __shfl_xor_sync(0xFFFFFFFFu, lp[cc], o);
    if (lane == 0) {
        #pragma unroll
        for (int cc = 0; cc < 4; cc++)
            logits[(size_t)r * NCLASS + cc] = lp[cc] + __ldg(cls_b + cc);
    }
}

// ---------------- launch ----------------
extern "C" void kernel_launch(void* const* d_in, const int* in_sizes, int n_in,
                              void* d_out, int out_size) {
    const float* x      = (const float*)d_in[0];
    const void*  rowp   = d_in[1];
    const void*  colp   = d_in[2];
    const float* asg_W1 = (const float*)d_in[3];
    const float* asg_b1 = (const float*)d_in[4];
    const float* asg_W2 = (const float*)d_in[5];
    const float* asg_b2 = (const float*)d_in[6];
    const float* lin_W  = (const float*)d_in[7];
    const float* lin_b  = (const float*)d_in[8];
    const float* conv_W = (const float*)d_in[9];
    const float* bias   = (const float*)d_in[10];
    const float* cls_W  = (const float*)d_in[11];
    const float* cls_b  = (const float*)d_in[12];

    int N = in_sizes[0] / NFEAT;
    int E = in_sizes[1];

    float* hout   = (float*)d_out;
    float* logits = hout + (size_t)N * HIDDEN;

    k_detect<<<1, 32>>>((const unsigned int*)rowp, E);
    k_fold<<<HIDDEN, NFEAT>>>(conv_W, lin_W, lin_b);
    k_proj<<<(N + 7) / 8, 256>>>(x, asg_W1, N);
    dim3 gg((N + BM - 1) / BM, HIDDEN / BN);
    k_cgemm<<<gg, 256>>>(x, N);
    k_zero<<<(N + 255) / 256, 256>>>(N);
    k_hist<<<(E + 255) / 256, 256>>>(rowp, E);
    k_scan<<<1, 1024>>>(N);
    k_scatter<<<(E + 255) / 256, 256>>>(rowp, colp, E);
    k_agg<<<(N + 7) / 8, 256>>>(asg_b1, asg_W2, asg_b2, bias,
                                cls_W, cls_b, hout, logits, N);
}

// round 5
// speedup vs baseline: 1.6727x; 1.5778x over previous
#include <cuda_runtime.h>
#include <math.h>

#define NFEAT   256
#define HIDDEN  256
#define PCH     64
#define NCLASS  4
#define MAXN    100000
#define MAXE    1600000

typedef unsigned long long ull;

__device__ __forceinline__ ull pack2(float x, float y) {
    ull r; asm("mov.b64 %0, {%1,%2};" : "=l"(r) : "f"(x), "f"(y)); return r;
}
__device__ __forceinline__ void unpack2(ull v, float& x, float& y) {
    asm("mov.b64 {%0,%1}, %2;" : "=f"(x), "=f"(y) : "l"(v));
}
__device__ __forceinline__ void ffma2(ull& d, ull a, ull b) {
    asm("fma.rn.f32x2 %0, %1, %2, %0;" : "+l"(d) : "l"(a), "l"(b));
}

// ---------------- device scratch ----------------
__device__ int   g_is64;
__device__ float g_CW[HIDDEN * NFEAT];
__device__ float g_cb[HIDDEN];
__device__ float g_proj[MAXN * 8];          // [pa0..3, pb0..3] per node
__device__ float g_c[(size_t)MAXN * HIDDEN];
__device__ int   g_counts[MAXN];
__device__ int   g_rowstart[MAXN];
__device__ int   g_cursor[MAXN];
__device__ int   g_csrcol[MAXE];

// ---------------- index width sniffing ----------------
__global__ void k_detect(const unsigned int* __restrict__ rowp, int E) {
    if (threadIdx.x == 0 && blockIdx.x == 0) {
        int n = E < 64 ? E : 64;
        int all_hi_zero = 1;
        for (int i = 0; i < n; i++)
            if (rowp[2 * i + 1] != 0u) { all_hi_zero = 0; break; }
        g_is64 = all_hi_zero;
    }
}

// ---------------- fold conv into lin ----------------
__global__ void k_fold(const float* __restrict__ conv_W,
                       const float* __restrict__ lin_W,
                       const float* __restrict__ lin_b) {
    int t = blockIdx.x, f = threadIdx.x;
    int k = t >> 6, q = t & 63;
    const float* cw = conv_W + (k * PCH + q) * PCH;
    const float* lw = lin_W + (size_t)k * PCH * NFEAT;
    float s = 0.f;
    #pragma unroll 8
    for (int p = 0; p < PCH; p++) s = fmaf(cw[p], lw[p * NFEAT + f], s);
    g_CW[t * NFEAT + f] = s;
    if (f == 0) {
        const float* lb = lin_b + k * PCH;
        float b = 0.f;
        for (int p = 0; p < PCH; p++) b = fmaf(cw[p], lb[p], b);
        g_cb[t] = b;
    }
}

// ---------------- per-node assignment projections ----------------
__global__ void k_proj(const float* __restrict__ x,
                       const float* __restrict__ asg_W1, int N) {
    int warp = (blockIdx.x * blockDim.x + threadIdx.x) >> 5;
    int lane = threadIdx.x & 31;
    if (warp >= N) return;
    const float* xr = x + (size_t)warp * NFEAT;
    float pa[4] = {0,0,0,0}, pb[4] = {0,0,0,0};
    #pragma unroll
    for (int t = 0; t < 8; t++) {
        int f = lane + 32 * t;
        float xv = xr[f];
        #pragma unroll
        for (int c = 0; c < 4; c++) {
            pa[c] = fmaf(xv, asg_W1[c * 512 + f], pa[c]);
            pb[c] = fmaf(xv, asg_W1[c * 512 + 256 + f], pb[c]);
        }
    }
    #pragma unroll
    for (int c = 0; c < 4; c++)
        #pragma unroll
        for (int o = 16; o > 0; o >>= 1) {
            pa[c] += __shfl_xor_sync(0xFFFFFFFFu, pa[c], o);
            pb[c] += __shfl_xor_sync(0xFFFFFFFFu, pb[c], o);
        }
    if (lane == 0) {
        #pragma unroll
        for (int c = 0; c < 4; c++) {
            g_proj[warp * 8 + c]     = pa[c];
            g_proj[warp * 8 + 4 + c] = pb[c];
        }
    }
}

// ---------------- c = X @ CW^T + cb  (double-buffered, f32x2 FMA) ----------------
#define BM 128
#define BN 128
#define BK 8
__global__ __launch_bounds__(256, 2)
void k_cgemm(const float* __restrict__ X, int N) {
    __shared__ float As[2][BK][BM + 4];
    __shared__ float Bs[2][BK][BN + 4];
    int m0 = blockIdx.x * BM, n0 = blockIdx.y * BN;
    int tid = threadIdx.x;
    int ty = tid >> 4, tx = tid & 15;
    int lm = tid >> 1, lf = (tid & 1) * 4;
    int gm = m0 + lm;

    ull accp[8][4];
    #pragma unroll
    for (int i = 0; i < 8; i++)
        #pragma unroll
        for (int j = 0; j < 4; j++) accp[i][j] = 0ull;

    // preload tile 0
    {
        float4 av = (gm < N) ? *(const float4*)(X + (size_t)gm * NFEAT + lf)
                             : make_float4(0.f,0.f,0.f,0.f);
        As[0][lf+0][lm] = av.x; As[0][lf+1][lm] = av.y;
        As[0][lf+2][lm] = av.z; As[0][lf+3][lm] = av.w;
        float4 bv = *(const float4*)(g_CW + (n0 + lm) * NFEAT + lf);
        Bs[0][lf+0][lm] = bv.x; Bs[0][lf+1][lm] = bv.y;
        Bs[0][lf+2][lm] = bv.z; Bs[0][lf+3][lm] = bv.w;
    }
    __syncthreads();

    int p = 0;
    for (int k0 = 0; k0 < NFEAT; k0 += BK) {
        float4 av, bv;
        bool pref = (k0 + BK < NFEAT);
        if (pref) {
            av = (gm < N) ? *(const float4*)(X + (size_t)gm * NFEAT + k0 + BK + lf)
                          : make_float4(0.f,0.f,0.f,0.f);
            bv = *(const float4*)(g_CW + (n0 + lm) * NFEAT + k0 + BK + lf);
        }
        #pragma unroll
        for (int kk = 0; kk < BK; kk++) {
            float a[8];
            *(float4*)&a[0] = *(const float4*)&As[p][kk][ty * 8];
            *(float4*)&a[4] = *(const float4*)&As[p][kk][ty * 8 + 4];
            ull b2[4];
            {
                ulonglong2 t0 = *(const ulonglong2*)&Bs[p][kk][tx * 8];
                ulonglong2 t1 = *(const ulonglong2*)&Bs[p][kk][tx * 8 + 4];
                b2[0] = t0.x; b2[1] = t0.y; b2[2] = t1.x; b2[3] = t1.y;
            }
            ull a2[8];
            #pragma unroll
            for (int i = 0; i < 8; i++) a2[i] = pack2(a[i], a[i]);
            #pragma unroll
            for (int i = 0; i < 8; i++)
                #pragma unroll
                for (int j = 0; j < 4; j++)
                    ffma2(accp[i][j], a2[i], b2[j]);
        }
        if (pref) {
            int q = p ^ 1;
            As[q][lf+0][lm] = av.x; As[q][lf+1][lm] = av.y;
            As[q][lf+2][lm] = av.z; As[q][lf+3][lm] = av.w;
            Bs[q][lf+0][lm] = bv.x; Bs[q][lf+1][lm] = bv.y;
            Bs[q][lf+2][lm] = bv.z; Bs[q][lf+3][lm] = bv.w;
        }
        __syncthreads();
        p ^= 1;
    }

    #pragma unroll
    for (int i = 0; i < 8; i++) {
        int om = m0 + ty * 8 + i;
        if (om >= N) break;
        float o[8];
        #pragma unroll
        for (int j = 0; j < 4; j++) unpack2(accp[i][j], o[2*j], o[2*j+1]);
        float* outp = g_c + (size_t)om * HIDDEN + n0 + tx * 8;
        #pragma unroll
        for (int j = 0; j < 8; j += 4) {
            float4 v;
            v.x = o[j+0] + g_cb[n0 + tx*8 + j+0];
            v.y = o[j+1] + g_cb[n0 + tx*8 + j+1];
            v.z = o[j+2] + g_cb[n0 + tx*8 + j+2];
            v.w = o[j+3] + g_cb[n0 + tx*8 + j+3];
            *(float4*)(outp + j) = v;
        }
    }
}

// ---------------- CSR build ----------------
__global__ void k_zero(int N) {
    int i = blockIdx.x * blockDim.x + threadIdx.x;
    if (i < N) g_counts[i] = 0;
}

__global__ void k_hist(const void* __restrict__ rowp, int E) {
    int e = blockIdx.x * blockDim.x + threadIdx.x;
    if (e >= E) return;
    int r = g_is64 ? (int)((const long long*)rowp)[e] : ((const int*)rowp)[e];
    atomicAdd(&g_counts[r], 1);
}

__global__ void k_scan(int N) {
    __shared__ int sh[1024];
    int tid = threadIdx.x;
    int chunk = (N + 1023) >> 10;
    int lo = tid * chunk;
    int hi = lo + chunk; if (hi > N) hi = N; if (lo > N) lo = N;
    int s = 0;
    for (int i = lo; i < hi; i++) s += g_counts[i];
    sh[tid] = s;
    __syncthreads();
    int v = s;
    for (int o = 1; o < 1024; o <<= 1) {
        int u = (tid >= o) ? sh[tid - o] : 0;
        __syncthreads();
        v += u;
        sh[tid] = v;
        __syncthreads();
    }
    int run = v - s;
    for (int i = lo; i < hi; i++) {
        g_rowstart[i] = run;
        g_cursor[i]   = run;
        run += g_counts[i];
    }
}

__global__ void k_scatter(const void* __restrict__ rowp,
                          const void* __restrict__ colp, int E) {
    int e = blockIdx.x * blockDim.x + threadIdx.x;
    if (e >= E) return;
    int r, c;
    if (g_is64) {
        r = (int)((const long long*)rowp)[e];
        c = (int)((const long long*)colp)[e];
    } else {
        r = ((const int*)rowp)[e];
        c = ((const int*)colp)[e];
    }
    int pos = atomicAdd(&g_cursor[r], 1);
    g_csrcol[pos] = c;
}

// ---------------- fused aggregate + bias + norm + classifier ----------------
__global__ __launch_bounds__(256)
void k_agg(const float* __restrict__ asg_b1, const float* __restrict__ asg_W2,
           const float* __restrict__ asg_b2, const float* __restrict__ bias,
           const float* __restrict__ cls_W, const float* __restrict__ cls_b,
           float* __restrict__ hout, float* __restrict__ logits, int N) {
    __shared__ float sw[8][32][4];   // weights per warp/edge/group
    __shared__ int   sc[8][32];      // col per warp/edge

    int wid  = threadIdx.x >> 5;
    int lane = threadIdx.x & 31;
    int r    = blockIdx.x * 8 + wid;
    if (r >= N) return;

    float b1[4], b2r[4], W2[16];
    #pragma unroll
    for (int k = 0; k < 4; k++) { b1[k] = __ldg(asg_b1 + k); b2r[k] = __ldg(asg_b2 + k); }
    #pragma unroll
    for (int k = 0; k < 16; k++) W2[k] = __ldg(asg_W2 + k);

    float4 pbv = *(const float4*)(g_proj + r * 8 + 4);
    float pb[4] = {pbv.x, pbv.y, pbv.z, pbv.w};

    int start = g_rowstart[r];
    int deg   = g_counts[r];
    int myg   = lane >> 3;           // group of this lane's 8 columns

    ull ap0 = 0ull, ap1 = 0ull, ap2 = 0ull, ap3 = 0ull;

    for (int base = 0; base < deg; base += 32) {
        int cnt = deg - base; if (cnt > 32) cnt = 32;
        float w0 = 0.f, w1 = 0.f, w2 = 0.f, w3 = 0.f;
        int   mycol = 0;
        if (lane < cnt) {
            mycol = g_csrcol[start + base + lane];
            float4 pav = __ldg((const float4*)(g_proj + (size_t)mycol * 8));
            float h1[4] = {pav.x + pb[0] + b1[0], pav.y + pb[1] + b1[1],
                           pav.z + pb[2] + b1[2], pav.w + pb[3] + b1[3]};
            float h2[4], mx = -1e30f;
            #pragma unroll
            for (int k = 0; k < 4; k++) {
                float s = b2r[k];
                #pragma unroll
                for (int d = 0; d < 4; d++) s = fmaf(h1[d], W2[k*4+d], s);
                h2[k] = s; mx = fmaxf(mx, s);
            }
            float e0 = __expf(h2[0]-mx), e1 = __expf(h2[1]-mx);
            float e2 = __expf(h2[2]-mx), e3 = __expf(h2[3]-mx);
            float inv = 1.f / (e0+e1+e2+e3);
            w0 = e0*inv; w1 = e1*inv; w2 = e2*inv; w3 = e3*inv;
        }
        sw[wid][lane][0] = w0; sw[wid][lane][1] = w1;
        sw[wid][lane][2] = w2; sw[wid][lane][3] = w3;
        sc[wid][lane] = mycol;
        __syncwarp();

        #pragma unroll 4
        for (int j = 0; j < cnt; j++) {
            int   cj = sc[wid][j];
            float wj = sw[wid][j][myg];
            ull   wj2 = pack2(wj, wj);
            const ulonglong2* cr =
                (const ulonglong2*)(g_c + (size_t)cj * HIDDEN) + lane * 2;
            ulonglong2 v0 = __ldg(cr);
            ulonglong2 v1 = __ldg(cr + 1);
            ffma2(ap0, v0.x, wj2); ffma2(ap1, v0.y, wj2);
            ffma2(ap2, v1.x, wj2); ffma2(ap3, v1.y, wj2);
        }
        __syncwarp();
    }

    float a[8];
    unpack2(ap0, a[0], a[1]); unpack2(ap1, a[2], a[3]);
    unpack2(ap2, a[4], a[5]); unpack2(ap3, a[6], a[7]);

    // bias + per-group L2 norm (each lane's 8 cols all in group myg)
    float4 bb0 = __ldg((const float4*)bias + lane * 2);
    float4 bb1 = __ldg((const float4*)bias + lane * 2 + 1);
    a[0] += bb0.x; a[1] += bb0.y; a[2] += bb0.z; a[3] += bb0.w;
    a[4] += bb1.x; a[5] += bb1.y; a[6] += bb1.z; a[7] += bb1.w;

    float ss = 0.f;
    #pragma unroll
    for (int t = 0; t < 8; t++) ss = fmaf(a[t], a[t], ss);
    #pragma unroll
    for (int o = 1; o < 8; o <<= 1)
        ss += __shfl_xor_sync(0xFFFFFFFFu, ss, o);   // reduce within 8-lane group
    float invn = 1.f / fmaxf(sqrtf(ss), 1e-12f);
    #pragma unroll
    for (int t = 0; t < 8; t++) a[t] *= invn;

    float4* hr = (float4*)(hout + (size_t)r * HIDDEN) + lane * 2;
    hr[0] = make_float4(a[0], a[1], a[2], a[3]);
    hr[1] = make_float4(a[4], a[5], a[6], a[7]);

    float lp[4];
    #pragma unroll
    for (int cc = 0; cc < 4; cc++) {
        const float4* cwp = (const float4*)(cls_W + cc * HIDDEN) + lane * 2;
        float4 c0 = __ldg(cwp), c1 = __ldg(cwp + 1);
        lp[cc] = a[0]*c0.x + a[1]*c0.y + a[2]*c0.z + a[3]*c0.w
               + a[4]*c1.x + a[5]*c1.y + a[6]*c1.z + a[7]*c1.w;
    }
    #pragma unroll
    for (int cc = 0; cc < 4; cc++)
        #pragma unroll
        for (int o = 16; o > 0; o >>= 1)
            lp[cc] += __shfl_xor_sync(0xFFFFFFFFu, lp[cc], o);
    if (lane == 0) {
        #pragma unroll
        for (int cc = 0; cc < 4; cc++)
            logits[(size_t)r * NCLASS + cc] = lp[cc] + __ldg(cls_b + cc);
    }
}

// ---------------- launch ----------------
extern "C" void kernel_launch(void* const* d_in, const int* in_sizes, int n_in,
                              void* d_out, int out_size) {
    const float* x      = (const float*)d_in[0];
    const void*  rowp   = d_in[1];
    const void*  colp   = d_in[2];
    const float* asg_W1 = (const float*)d_in[3];
    const float* asg_b1 = (const float*)d_in[4];
    const float* asg_W2 = (const float*)d_in[5];
    const float* asg_b2 = (const float*)d_in[6];
    const float* lin_W  = (const float*)d_in[7];
    const float* lin_b  = (const float*)d_in[8];
    const float* conv_W = (const float*)d_in[9];
    const float* bias   = (const float*)d_in[10];
    const float* cls_W  = (const float*)d_in[11];
    const float* cls_b  = (const float*)d_in[12];

    int N = in_sizes[0] / NFEAT;
    int E = in_sizes[1];

    float* hout   = (float*)d_out;
    float* logits = hout + (size_t)N * HIDDEN;

    k_detect<<<1, 32>>>((const unsigned int*)rowp, E);
    k_fold<<<HIDDEN, NFEAT>>>(conv_W, lin_W, lin_b);
    k_proj<<<(N + 7) / 8, 256>>>(x, asg_W1, N);
    dim3 gg((N + BM - 1) / BM, HIDDEN / BN);
    k_cgemm<<<gg, 256>>>(x, N);
    k_zero<<<(N + 255) / 256, 256>>>(N);
    k_hist<<<(E + 255) / 256, 256>>>(rowp, E);
    k_scan<<<1, 1024>>>(N);
    k_scatter<<<(E + 255) / 256, 256>>>(rowp, colp, E);
    k_agg<<<(N + 7) / 8, 256>>>(asg_b1, asg_W2, asg_b2, bias,
                                cls_W, cls_b, hout, logits, N);
}

// round 7
// speedup vs baseline: 2.0060x; 1.1993x over previous
#include <cuda_runtime.h>
#include <cuda_bf16.h>
#include <math.h>
#include <cstdint>

#define NFEAT   256
#define HIDDEN  256
#define PCH     64
#define NCLASS  4
#define MAXN    100000
#define MAXE    1600000

typedef unsigned long long ull;

__device__ __forceinline__ ull pack2(float x, float y) {
    ull r; asm("mov.b64 %0, {%1,%2};" : "=l"(r) : "f"(x), "f"(y)); return r;
}
__device__ __forceinline__ void unpack2(ull v, float& x, float& y) {
    asm("mov.b64 {%0,%1}, %2;" : "=f"(x), "=f"(y) : "l"(v));
}
__device__ __forceinline__ void ffma2(ull& d, ull a, ull b) {
    asm("fma.rn.f32x2 %0, %1, %2, %0;" : "+l"(d) : "l"(a), "l"(b));
}
__device__ __forceinline__ uint32_t smem_u32(const void* p) {
    uint32_t a;
    asm("{ .reg .u64 t; cvta.to.shared.u64 t, %1; cvt.u32.u64 %0, t; }"
        : "=r"(a) : "l"(p));
    return a;
}
__device__ __forceinline__ void ldsm4(uint32_t addr, uint32_t& r0, uint32_t& r1,
                                      uint32_t& r2, uint32_t& r3) {
    asm volatile("ldmatrix.sync.aligned.m8n8.x4.shared.b16 {%0,%1,%2,%3}, [%4];"
                 : "=r"(r0), "=r"(r1), "=r"(r2), "=r"(r3) : "r"(addr));
}
__device__ __forceinline__ void mma16816(float* c, uint32_t a0, uint32_t a1,
                                         uint32_t a2, uint32_t a3,
                                         uint32_t b0, uint32_t b1) {
    asm volatile(
        "mma.sync.aligned.m16n8k16.row.col.f32.bf16.bf16.f32 "
        "{%0,%1,%2,%3}, {%4,%5,%6,%7}, {%8,%9}, {%0,%1,%2,%3};"
        : "+f"(c[0]), "+f"(c[1]), "+f"(c[2]), "+f"(c[3])
        : "r"(a0), "r"(a1), "r"(a2), "r"(a3), "r"(b0), "r"(b1));
}

// ---------------- device scratch ----------------
__device__ int   g_is64;
__device__ float g_cb[HIDDEN];
__device__ float g_proj[MAXN * 8];
__device__ float g_c[(size_t)MAXN * HIDDEN];
__device__ __nv_bfloat16 g_xhi[(size_t)MAXN * NFEAT];
__device__ __nv_bfloat16 g_xlo[(size_t)MAXN * NFEAT];
__device__ __nv_bfloat16 g_cwhi[HIDDEN * NFEAT];
__device__ __nv_bfloat16 g_cwlo[HIDDEN * NFEAT];
__device__ int   g_counts[MAXN];
__device__ int   g_rowstart[MAXN];
__device__ int   g_cursor[MAXN];
__device__ int   g_csrcol[MAXE];

// ---------------- index width sniffing ----------------
__global__ void k_detect(const unsigned int* __restrict__ rowp, int E) {
    if (threadIdx.x == 0 && blockIdx.x == 0) {
        int n = E < 64 ? E : 64;
        int all_hi_zero = 1;
        for (int i = 0; i < n; i++)
            if (rowp[2 * i + 1] != 0u) { all_hi_zero = 0; break; }
        g_is64 = all_hi_zero;
    }
}

// ---------------- fold conv into lin, output bf16 hi/lo ----------------
__global__ void k_fold(const float* __restrict__ conv_W,
                       const float* __restrict__ lin_W,
                       const float* __restrict__ lin_b) {
    int t = blockIdx.x, f = threadIdx.x;
    int k = t >> 6, q = t & 63;
    const float* cw = conv_W + (k * PCH + q) * PCH;
    const float* lw = lin_W + (size_t)k * PCH * NFEAT;
    float s = 0.f;
    #pragma unroll 8
    for (int p = 0; p < PCH; p++) s = fmaf(cw[p], lw[p * NFEAT + f], s);
    __nv_bfloat16 hi = __float2bfloat16(s);
    g_cwhi[t * NFEAT + f] = hi;
    g_cwlo[t * NFEAT + f] = __float2bfloat16(s - __bfloat162float(hi));
    if (f == 0) {
        const float* lb = lin_b + k * PCH;
        float b = 0.f;
        for (int p = 0; p < PCH; p++) b = fmaf(cw[p], lb[p], b);
        g_cb[t] = b;
    }
}

// ---------------- projections + x split (single x read) ----------------
__global__ void k_proj(const float* __restrict__ x,
                       const float* __restrict__ asg_W1, int N) {
    int warp = (blockIdx.x * blockDim.x + threadIdx.x) >> 5;
    int lane = threadIdx.x & 31;
    if (warp >= N) return;
    const float* xr = x + (size_t)warp * NFEAT;
    float pa[4] = {0,0,0,0}, pb[4] = {0,0,0,0};
    #pragma unroll
    for (int t = 0; t < 8; t++) {
        int f = lane + 32 * t;
        float xv = xr[f];
        __nv_bfloat16 h = __float2bfloat16(xv);
        g_xhi[(size_t)warp * NFEAT + f] = h;
        g_xlo[(size_t)warp * NFEAT + f] =
            __float2bfloat16(xv - __bfloat162float(h));
        #pragma unroll
        for (int c = 0; c < 4; c++) {
            pa[c] = fmaf(xv, asg_W1[c * 512 + f], pa[c]);
            pb[c] = fmaf(xv, asg_W1[c * 512 + 256 + f], pb[c]);
        }
    }
    #pragma unroll
    for (int c = 0; c < 4; c++)
        #pragma unroll
        for (int o = 16; o > 0; o >>= 1) {
            pa[c] += __shfl_xor_sync(0xFFFFFFFFu, pa[c], o);
            pb[c] += __shfl_xor_sync(0xFFFFFFFFu, pb[c], o);
        }
    if (lane == 0) {
        #pragma unroll
        for (int c = 0; c < 4; c++) {
            g_proj[warp * 8 + c]     = pa[c];
            g_proj[warp * 8 + 4 + c] = pb[c];
        }
    }
}

// ---------------- c = X @ CW^T + cb  via mma.sync bf16 split ----------------
// block tile 128x128, 8 warps (4m x 2n), warp tile 32x64
// K chunked by 32; smem rows pitched 80B (64B data + 16 pad) -> ldsm conflict-free
#define CHK 32
#define PITCH 80
#define T_AH 0
#define T_AL (128 * PITCH)
#define T_BH (2 * 128 * PITCH)
#define T_BL (3 * 128 * PITCH)

__global__ __launch_bounds__(256)
void k_cmma(int N) {
    __shared__ __align__(16) char sm[4 * 128 * PITCH];   // 40 KB
    uint32_t sb = smem_u32(sm);
    int tid  = threadIdx.x;
    int wid  = tid >> 5;
    int lane = tid & 31;
    int m0 = blockIdx.x * 128;
    int n0 = blockIdx.y * 128;
    int warp_m = wid >> 1;          // 0..3
    int warp_n = wid & 1;           // 0..1

    float acc[2][8][4];
    #pragma unroll
    for (int i = 0; i < 2; i++)
        #pragma unroll
        for (int j = 0; j < 8; j++)
            #pragma unroll
            for (int q = 0; q < 4; q++) acc[i][j][q] = 0.f;

    // precomputed fragment smem addresses (chunk-local, updated by kk)
    int a_row = warp_m * 32 + (lane & 15);
    int a_col = (lane >> 4) << 3;
    uint32_t aoff = (uint32_t)(a_row * PITCH + a_col * 2);
    int b_row_base = warp_n * 64 + ((lane >> 4) << 3) + (lane & 7);
    int b_col = ((lane >> 3) & 1) << 3;
    uint32_t boff = (uint32_t)(b_row_base * PITCH + b_col * 2);

    int lrow = tid >> 2;          // 0..63
    int lseg = tid & 3;           // 16B segment (8 bf16)

    for (int k0 = 0; k0 < NFEAT; k0 += CHK) {
        // ---- load smem tiles ----
        #pragma unroll
        for (int ps = 0; ps < 2; ps++) {
            int r = lrow + ps * 64;
            uint32_t dst = (uint32_t)(r * PITCH + lseg * 16);
            int gm = m0 + r;
            uint4 vh, vl;
            if (gm < N) {
                vh = *(const uint4*)(g_xhi + (size_t)gm * NFEAT + k0 + lseg * 8);
                vl = *(const uint4*)(g_xlo + (size_t)gm * NFEAT + k0 + lseg * 8);
            } else {
                vh = make_uint4(0,0,0,0); vl = make_uint4(0,0,0,0);
            }
            *(uint4*)(sm + T_AH + dst) = vh;
            *(uint4*)(sm + T_AL + dst) = vl;
            int gn = n0 + r;
            *(uint4*)(sm + T_BH + dst) =
                *(const uint4*)(g_cwhi + (size_t)gn * NFEAT + k0 + lseg * 8);
            *(uint4*)(sm + T_BL + dst) =
                *(const uint4*)(g_cwlo + (size_t)gn * NFEAT + k0 + lseg * 8);
        }
        __syncthreads();

        #pragma unroll
        for (int ka = 0; ka < CHK / 16; ka++) {
            uint32_t kb = (uint32_t)(ka * 16 * 2);
            uint32_t ah[2][4], al[2][4];
            #pragma unroll
            for (int i = 0; i < 2; i++) {
                uint32_t aa = sb + aoff + kb + (uint32_t)(i * 16 * PITCH);
                ldsm4(aa + T_AH, ah[i][0], ah[i][1], ah[i][2], ah[i][3]);
                ldsm4(aa + T_AL, al[i][0], al[i][1], al[i][2], al[i][3]);
            }
            #pragma unroll
            for (int jp = 0; jp < 4; jp++) {
                uint32_t ba = sb + boff + kb + (uint32_t)(jp * 16 * PITCH);
                uint32_t bh[4], bl[4];
                ldsm4(ba + T_BH, bh[0], bh[1], bh[2], bh[3]);
                ldsm4(ba + T_BL, bl[0], bl[1], bl[2], bl[3]);
                #pragma unroll
                for (int i = 0; i < 2; i++) {
                    float* c0 = acc[i][2 * jp];
                    float* c1 = acc[i][2 * jp + 1];
                    mma16816(c0, ah[i][0], ah[i][1], ah[i][2], ah[i][3], bh[0], bh[1]);
                    mma16816(c0, al[i][0], al[i][1], al[i][2], al[i][3], bh[0], bh[1]);
                    mma16816(c0, ah[i][0], ah[i][1], ah[i][2], ah[i][3], bl[0], bl[1]);
                    mma16816(c1, ah[i][0], ah[i][1], ah[i][2], ah[i][3], bh[2], bh[3]);
                    mma16816(c1, al[i][0], al[i][1], al[i][2], al[i][3], bh[2], bh[3]);
                    mma16816(c1, ah[i][0], ah[i][1], ah[i][2], ah[i][3], bl[2], bl[3]);
                }
            }
        }
        __syncthreads();
    }

    // ---- epilogue: write g_c with bias ----
    int g = lane >> 2, t4 = lane & 3;
    #pragma unroll
    for (int i = 0; i < 2; i++) {
        int row0 = m0 + warp_m * 32 + i * 16 + g;
        #pragma unroll
        for (int j = 0; j < 8; j++) {
            int col = n0 + warp_n * 64 + j * 8 + 2 * t4;
            float cb0 = g_cb[col], cb1 = g_cb[col + 1];
            if (row0 < N) {
                float2 v = make_float2(acc[i][j][0] + cb0, acc[i][j][1] + cb1);
                *(float2*)(g_c + (size_t)row0 * HIDDEN + col) = v;
            }
            if (row0 + 8 < N) {
                float2 v = make_float2(acc[i][j][2] + cb0, acc[i][j][3] + cb1);
                *(float2*)(g_c + (size_t)(row0 + 8) * HIDDEN + col) = v;
            }
        }
    }
}

// ---------------- CSR build ----------------
__global__ void k_zero(int N) {
    int i = blockIdx.x * blockDim.x + threadIdx.x;
    if (i < N) g_counts[i] = 0;
}

__global__ void k_hist(const void* __restrict__ rowp, int E) {
    int e = blockIdx.x * blockDim.x + threadIdx.x;
    if (e >= E) return;
    int r = g_is64 ? (int)((const long long*)rowp)[e] : ((const int*)rowp)[e];
    atomicAdd(&g_counts[r], 1);
}

__global__ void k_scan(int N) {
    __shared__ int sh[1024];
    int tid = threadIdx.x;
    int chunk = (N + 1023) >> 10;
    int lo = tid * chunk;
    int hi = lo + chunk; if (hi > N) hi = N; if (lo > N) lo = N;
    int s = 0;
    for (int i = lo; i < hi; i++) s += g_counts[i];
    sh[tid] = s;
    __syncthreads();
    int v = s;
    for (int o = 1; o < 1024; o <<= 1) {
        int u = (tid >= o) ? sh[tid - o] : 0;
        __syncthreads();
        v += u;
        sh[tid] = v;
        __syncthreads();
    }
    int run = v - s;
    for (int i = lo; i < hi; i++) {
        g_rowstart[i] = run;
        g_cursor[i]   = run;
        run += g_counts[i];
    }
}

__global__ void k_scatter(const void* __restrict__ rowp,
                          const void* __restrict__ colp, int E) {
    int e = blockIdx.x * blockDim.x + threadIdx.x;
    if (e >= E) return;
    int r, c;
    if (g_is64) {
        r = (int)((const long long*)rowp)[e];
        c = (int)((const long long*)colp)[e];
    } else {
        r = ((const int*)rowp)[e];
        c = ((const int*)colp)[e];
    }
    int pos = atomicAdd(&g_cursor[r], 1);
    g_csrcol[pos] = c;
}

// ---------------- fused aggregate + bias + norm + classifier ----------------
__global__ __launch_bounds__(256)
void k_agg(const float* __restrict__ asg_b1, const float* __restrict__ asg_W2,
           const float* __restrict__ asg_b2, const float* __restrict__ bias,
           const float* __restrict__ cls_W, const float* __restrict__ cls_b,
           float* __restrict__ hout, float* __restrict__ logits, int N) {
    __shared__ float sw[8][32][4];
    __shared__ int   sc[8][32];

    int wid  = threadIdx.x >> 5;
    int lane = threadIdx.x & 31;
    int r    = blockIdx.x * 8 + wid;
    if (r >= N) return;

    float b1[4], b2r[4], W2[16];
    #pragma unroll
    for (int k = 0; k < 4; k++) { b1[k] = __ldg(asg_b1 + k); b2r[k] = __ldg(asg_b2 + k); }
    #pragma unroll
    for (int k = 0; k < 16; k++) W2[k] = __ldg(asg_W2 + k);

    float4 pbv = *(const float4*)(g_proj + r * 8 + 4);
    float pb[4] = {pbv.x, pbv.y, pbv.z, pbv.w};

    int start = g_rowstart[r];
    int deg   = g_counts[r];
    int myg   = lane >> 3;

    ull ap0 = 0ull, ap1 = 0ull, ap2 = 0ull, ap3 = 0ull;

    for (int base = 0; base < deg; base += 32) {
        int cnt = deg - base; if (cnt > 32) cnt = 32;
        float w0 = 0.f, w1 = 0.f, w2 = 0.f, w3 = 0.f;
        int   mycol = 0;
        if (lane < cnt) {
            mycol = g_csrcol[start + base + lane];
            float4 pav = __ldg((const float4*)(g_proj + (size_t)mycol * 8));
            float h1[4] = {pav.x + pb[0] + b1[0], pav.y + pb[1] + b1[1],
                           pav.z + pb[2] + b1[2], pav.w + pb[3] + b1[3]};
            float h2[4], mx = -1e30f;
            #pragma unroll
            for (int k = 0; k < 4; k++) {
                float s = b2r[k];
                #pragma unroll
                for (int d = 0; d < 4; d++) s = fmaf(h1[d], W2[k*4+d], s);
                h2[k] = s; mx = fmaxf(mx, s);
            }
            float e0 = __expf(h2[0]-mx), e1 = __expf(h2[1]-mx);
            float e2 = __expf(h2[2]-mx), e3 = __expf(h2[3]-mx);
            float inv = 1.f / (e0+e1+e2+e3);
            w0 = e0*inv; w1 = e1*inv; w2 = e2*inv; w3 = e3*inv;
        }
        sw[wid][lane][0] = w0; sw[wid][lane][1] = w1;
        sw[wid][lane][2] = w2; sw[wid][lane][3] = w3;
        sc[wid][lane] = mycol;
        __syncwarp();

        #pragma unroll 4
        for (int j = 0; j < cnt; j++) {
            int   cj = sc[wid][j];
            float wj = sw[wid][j][myg];
            ull   wj2 = pack2(wj, wj);
            const ulonglong2* cr =
                (const ulonglong2*)(g_c + (size_t)cj * HIDDEN) + lane * 2;
            ulonglong2 v0 = __ldg(cr);
            ulonglong2 v1 = __ldg(cr + 1);
            ffma2(ap0, v0.x, wj2); ffma2(ap1, v0.y, wj2);
            ffma2(ap2, v1.x, wj2); ffma2(ap3, v1.y, wj2);
        }
        __syncwarp();
    }

    float a[8];
    unpack2(ap0, a[0], a[1]); unpack2(ap1, a[2], a[3]);
    unpack2(ap2, a[4], a[5]); unpack2(ap3, a[6], a[7]);

    float4 bb0 = __ldg((const float4*)bias + lane * 2);
    float4 bb1 = __ldg((const float4*)bias + lane * 2 + 1);
    a[0] += bb0.x; a[1] += bb0.y; a[2] += bb0.z; a[3] += bb0.w;
    a[4] += bb1.x; a[5] += bb1.y; a[6] += bb1.z; a[7] += bb1.w;

    float ss = 0.f;
    #pragma unroll
    for (int t = 0; t < 8; t++) ss = fmaf(a[t], a[t], ss);
    #pragma unroll
    for (int o = 1; o < 8; o <<= 1)
        ss += __shfl_xor_sync(0xFFFFFFFFu, ss, o);
    float invn = 1.f / fmaxf(sqrtf(ss), 1e-12f);
    #pragma unroll
    for (int t = 0; t < 8; t++) a[t] *= invn;

    float4* hr = (float4*)(hout + (size_t)r * HIDDEN) + lane * 2;
    hr[0] = make_float4(a[0], a[1], a[2], a[3]);
    hr[1] = make_float4(a[4], a[5], a[6], a[7]);

    float lp[4];
    #pragma unroll
    for (int cc = 0; cc < 4; cc++) {
        const float4* cwp = (const float4*)(cls_W + cc * HIDDEN) + lane * 2;
        float4 c0 = __ldg(cwp), c1 = __ldg(cwp + 1);
        lp[cc] = a[0]*c0.x + a[1]*c0.y + a[2]*c0.z + a[3]*c0.w
               + a[4]*c1.x + a[5]*c1.y + a[6]*c1.z + a[7]*c1.w;
    }
    #pragma unroll
    for (int cc = 0; cc < 4; cc++)
        #pragma unroll
        for (int o = 16; o > 0; o >>= 1)
            lp[cc] += __shfl_xor_sync(0xFFFFFFFFu, lp[cc], o);
    if (lane == 0) {
        #pragma unroll
        for (int cc = 0; cc < 4; cc++)
            logits[(size_t)r * NCLASS + cc] = lp[cc] + __ldg(cls_b + cc);
    }
}

// ---------------- launch ----------------
extern "C" void kernel_launch(void* const* d_in, const int* in_sizes, int n_in,
                              void* d_out, int out_size) {
    const float* x      = (const float*)d_in[0];
    const void*  rowp   = d_in[1];
    const void*  colp   = d_in[2];
    const float* asg_W1 = (const float*)d_in[3];
    const float* asg_b1 = (const float*)d_in[4];
    const float* asg_W2 = (const float*)d_in[5];
    const float* asg_b2 = (const float*)d_in[6];
    const float* lin_W  = (const float*)d_in[7];
    const float* lin_b  = (const float*)d_in[8];
    const float* conv_W = (const float*)d_in[9];
    const float* bias   = (const float*)d_in[10];
    const float* cls_W  = (const float*)d_in[11];
    const float* cls_b  = (const float*)d_in[12];

    int N = in_sizes[0] / NFEAT;
    int E = in_sizes[1];

    float* hout   = (float*)d_out;
    float* logits = hout + (size_t)N * HIDDEN;

    k_detect<<<1, 32>>>((const unsigned int*)rowp, E);
    k_fold<<<HIDDEN, NFEAT>>>(conv_W, lin_W, lin_b);
    k_proj<<<(N + 7) / 8, 256>>>(x, asg_W1, N);
    dim3 gg((N + 127) / 128, HIDDEN / 128);
    k_cmma<<<gg, 256>>>(N);
    k_zero<<<(N + 255) / 256, 256>>>(N);
    k_hist<<<(E + 255) / 256, 256>>>(rowp, E);
    k_scan<<<1, 1024>>>(N);
    k_scatter<<<(E + 255) / 256, 256>>>(rowp, colp, E);
    k_agg<<<(N + 7) / 8, 256>>>(asg_b1, asg_W2, asg_b2, bias,
                                cls_W, cls_b, hout, logits, N);
}

// round 8
// speedup vs baseline: 2.2286x; 1.1110x over previous
#include <cuda_runtime.h>
#include <cuda_bf16.h>
#include <math.h>
#include <cstdint>

#define NFEAT   256
#define HIDDEN  256
#define PCH     64
#define NCLASS  4
#define MAXN    100000
#define MAXE    1600000

typedef unsigned long long ull;

__device__ __forceinline__ ull pack2(float x, float y) {
    ull r; asm("mov.b64 %0, {%1,%2};" : "=l"(r) : "f"(x), "f"(y)); return r;
}
__device__ __forceinline__ void unpack2(ull v, float& x, float& y) {
    asm("mov.b64 {%0,%1}, %2;" : "=f"(x), "=f"(y) : "l"(v));
}
__device__ __forceinline__ void ffma2(ull& d, ull a, ull b) {
    asm("fma.rn.f32x2 %0, %1, %2, %0;" : "+l"(d) : "l"(a), "l"(b));
}
__device__ __forceinline__ uint32_t smem_u32(const void* p) {
    uint32_t a;
    asm("{ .reg .u64 t; cvta.to.shared.u64 t, %1; cvt.u32.u64 %0, t; }"
        : "=r"(a) : "l"(p));
    return a;
}
__device__ __forceinline__ void ldsm4(uint32_t addr, uint32_t& r0, uint32_t& r1,
                                      uint32_t& r2, uint32_t& r3) {
    asm volatile("ldmatrix.sync.aligned.m8n8.x4.shared.b16 {%0,%1,%2,%3}, [%4];"
                 : "=r"(r0), "=r"(r1), "=r"(r2), "=r"(r3) : "r"(addr));
}
__device__ __forceinline__ void mma16816(float* c, uint32_t a0, uint32_t a1,
                                         uint32_t a2, uint32_t a3,
                                         uint32_t b0, uint32_t b1) {
    asm volatile(
        "mma.sync.aligned.m16n8k16.row.col.f32.bf16.bf16.f32 "
        "{%0,%1,%2,%3}, {%4,%5,%6,%7}, {%8,%9}, {%0,%1,%2,%3};"
        : "+f"(c[0]), "+f"(c[1]), "+f"(c[2]), "+f"(c[3])
        : "r"(a0), "r"(a1), "r"(a2), "r"(a3), "r"(b0), "r"(b1));
}
__device__ __forceinline__ void cp16z(uint32_t dst, const void* src, int inb) {
    int sz = inb ? 16 : 0;
    asm volatile("cp.async.cg.shared.global [%0], [%1], 16, %2;"
                 :: "r"(dst), "l"(src), "r"(sz));
}
__device__ __forceinline__ void cp16(uint32_t dst, const void* src) {
    asm volatile("cp.async.cg.shared.global [%0], [%1], 16;"
                 :: "r"(dst), "l"(src));
}

// ---------------- device scratch ----------------
__device__ int   g_is64;
__device__ float g_cb[HIDDEN];
__device__ float g_proj[MAXN * 8];
__device__ float g_c[(size_t)MAXN * HIDDEN];
__device__ __nv_bfloat16 g_xhi[(size_t)MAXN * NFEAT];
__device__ __nv_bfloat16 g_xlo[(size_t)MAXN * NFEAT];
__device__ __nv_bfloat16 g_cwhi[HIDDEN * NFEAT];
__device__ __nv_bfloat16 g_cwlo[HIDDEN * NFEAT];
__device__ int   g_counts[MAXN];
__device__ int   g_rowstart[MAXN];
__device__ int   g_cursor[MAXN];
__device__ int   g_csrcol[MAXE];

// ---------------- index width sniffing ----------------
__global__ void k_detect(const unsigned int* __restrict__ rowp, int E) {
    if (threadIdx.x == 0 && blockIdx.x == 0) {
        int n = E < 64 ? E : 64;
        int all_hi_zero = 1;
        for (int i = 0; i < n; i++)
            if (rowp[2 * i + 1] != 0u) { all_hi_zero = 0; break; }
        g_is64 = all_hi_zero;
    }
}

// ---------------- fold conv into lin, output bf16 hi/lo ----------------
__global__ void k_fold(const float* __restrict__ conv_W,
                       const float* __restrict__ lin_W,
                       const float* __restrict__ lin_b) {
    int t = blockIdx.x, f = threadIdx.x;
    int k = t >> 6, q = t & 63;
    const float* cw = conv_W + (k * PCH + q) * PCH;
    const float* lw = lin_W + (size_t)k * PCH * NFEAT;
    float s = 0.f;
    #pragma unroll 8
    for (int p = 0; p < PCH; p++) s = fmaf(cw[p], lw[p * NFEAT + f], s);
    __nv_bfloat16 hi = __float2bfloat16(s);
    g_cwhi[t * NFEAT + f] = hi;
    g_cwlo[t * NFEAT + f] = __float2bfloat16(s - __bfloat162float(hi));
    if (f == 0) {
        const float* lb = lin_b + k * PCH;
        float b = 0.f;
        for (int p = 0; p < PCH; p++) b = fmaf(cw[p], lb[p], b);
        g_cb[t] = b;
    }
}

// ---------------- projections + x split (single x read) ----------------
__global__ void k_proj(const float* __restrict__ x,
                       const float* __restrict__ asg_W1, int N) {
    int warp = (blockIdx.x * blockDim.x + threadIdx.x) >> 5;
    int lane = threadIdx.x & 31;
    if (warp >= N) return;
    const float* xr = x + (size_t)warp * NFEAT;
    float pa[4] = {0,0,0,0}, pb[4] = {0,0,0,0};
    #pragma unroll
    for (int t = 0; t < 8; t++) {
        int f = lane + 32 * t;
        float xv = xr[f];
        __nv_bfloat16 h = __float2bfloat16(xv);
        g_xhi[(size_t)warp * NFEAT + f] = h;
        g_xlo[(size_t)warp * NFEAT + f] =
            __float2bfloat16(xv - __bfloat162float(h));
        #pragma unroll
        for (int c = 0; c < 4; c++) {
            pa[c] = fmaf(xv, asg_W1[c * 512 + f], pa[c]);
            pb[c] = fmaf(xv, asg_W1[c * 512 + 256 + f], pb[c]);
        }
    }
    #pragma unroll
    for (int c = 0; c < 4; c++)
        #pragma unroll
        for (int o = 16; o > 0; o >>= 1) {
            pa[c] += __shfl_xor_sync(0xFFFFFFFFu, pa[c], o);
            pb[c] += __shfl_xor_sync(0xFFFFFFFFu, pb[c], o);
        }
    if (lane == 0) {
        #pragma unroll
        for (int c = 0; c < 4; c++) {
            g_proj[warp * 8 + c]     = pa[c];
            g_proj[warp * 8 + 4 + c] = pb[c];
        }
    }
}

// ---------------- c = X @ CW^T + cb  via mma.sync bf16 split ----------------
// block tile 128x128, 8 warps (4m x 2n), warp tile 32x64
// K chunked by 32; smem rows pitched 80B; cp.async double-buffered
#define CHK 32
#define PITCH 80
#define T_AH 0
#define T_AL (128 * PITCH)
#define T_BH (2 * 128 * PITCH)
#define T_BL (3 * 128 * PITCH)
#define STAGE_BYTES (4 * 128 * PITCH)
#define SM_DYN (2 * STAGE_BYTES)
#define NCHUNK (NFEAT / CHK)

__global__ __launch_bounds__(256, 2)
void k_cmma(int N) {
    extern __shared__ __align__(16) char sm[];
    uint32_t sb = smem_u32(sm);
    int tid  = threadIdx.x;
    int wid  = tid >> 5;
    int lane = tid & 31;
    int m0 = blockIdx.x * 128;
    int n0 = blockIdx.y * 128;
    int warp_m = wid >> 1;          // 0..3
    int warp_n = wid & 1;           // 0..1

    float acc[2][8][4];
    #pragma unroll
    for (int i = 0; i < 2; i++)
        #pragma unroll
        for (int j = 0; j < 8; j++)
            #pragma unroll
            for (int q = 0; q < 4; q++) acc[i][j][q] = 0.f;

    // fragment smem offsets (stage-local)
    int a_row = warp_m * 32 + (lane & 15);
    int a_col = (lane >> 4) << 3;
    uint32_t aoff = (uint32_t)(a_row * PITCH + a_col * 2);
    int b_row_base = warp_n * 64 + ((lane >> 4) << 3) + (lane & 7);
    int b_col = ((lane >> 3) & 1) << 3;
    uint32_t boff = (uint32_t)(b_row_base * PITCH + b_col * 2);

    int lrow = tid >> 2;          // 0..63
    int lseg = tid & 3;           // 16B segment (8 bf16)

    // ---- async loader for one chunk into stage s ----
    auto load_stage = [&](int s, int k0) {
        uint32_t sgb = sb + (uint32_t)(s * STAGE_BYTES);
        #pragma unroll
        for (int ps = 0; ps < 2; ps++) {
            int r = lrow + ps * 64;
            uint32_t dst = sgb + (uint32_t)(r * PITCH + lseg * 16);
            int gm = m0 + r;
            int inb = gm < N;
            const __nv_bfloat16* ah = g_xhi + (size_t)(inb ? gm : 0) * NFEAT + k0 + lseg * 8;
            const __nv_bfloat16* al = g_xlo + (size_t)(inb ? gm : 0) * NFEAT + k0 + lseg * 8;
            cp16z(dst + T_AH, ah, inb);
            cp16z(dst + T_AL, al, inb);
            int gn = n0 + r;
            cp16(dst + T_BH, g_cwhi + (size_t)gn * NFEAT + k0 + lseg * 8);
            cp16(dst + T_BL, g_cwlo + (size_t)gn * NFEAT + k0 + lseg * 8);
        }
        asm volatile("cp.async.commit_group;");
    };

    load_stage(0, 0);

    #pragma unroll 1
    for (int chunk = 0; chunk < NCHUNK; chunk++) {
        int s = chunk & 1;
        asm volatile("cp.async.wait_group 0;" ::: "memory");
        __syncthreads();
        if (chunk + 1 < NCHUNK) load_stage(s ^ 1, (chunk + 1) * CHK);

        uint32_t sgb = sb + (uint32_t)(s * STAGE_BYTES);
        #pragma unroll
        for (int ka = 0; ka < CHK / 16; ka++) {
            uint32_t kb = (uint32_t)(ka * 16 * 2);
            uint32_t ah[2][4], al[2][4];
            #pragma unroll
            for (int i = 0; i < 2; i++) {
                uint32_t aa = sgb + aoff + kb + (uint32_t)(i * 16 * PITCH);
                ldsm4(aa + T_AH, ah[i][0], ah[i][1], ah[i][2], ah[i][3]);
                ldsm4(aa + T_AL, al[i][0], al[i][1], al[i][2], al[i][3]);
            }
            #pragma unroll
            for (int jp = 0; jp < 4; jp++) {
                uint32_t ba = sgb + boff + kb + (uint32_t)(jp * 16 * PITCH);
                uint32_t bh[4], bl[4];
                ldsm4(ba + T_BH, bh[0], bh[1], bh[2], bh[3]);
                ldsm4(ba + T_BL, bl[0], bl[1], bl[2], bl[3]);
                #pragma unroll
                for (int i = 0; i < 2; i++) {
                    float* c0 = acc[i][2 * jp];
                    float* c1 = acc[i][2 * jp + 1];
                    mma16816(c0, ah[i][0], ah[i][1], ah[i][2], ah[i][3], bh[0], bh[1]);
                    mma16816(c0, al[i][0], al[i][1], al[i][2], al[i][3], bh[0], bh[1]);
                    mma16816(c0, ah[i][0], ah[i][1], ah[i][2], ah[i][3], bl[0], bl[1]);
                    mma16816(c1, ah[i][0], ah[i][1], ah[i][2], ah[i][3], bh[2], bh[3]);
                    mma16816(c1, al[i][0], al[i][1], al[i][2], al[i][3], bh[2], bh[3]);
                    mma16816(c1, ah[i][0], ah[i][1], ah[i][2], ah[i][3], bl[2], bl[3]);
                }
            }
        }
        __syncthreads();
    }

    // ---- epilogue: write g_c with bias ----
    int g = lane >> 2, t4 = lane & 3;
    #pragma unroll
    for (int i = 0; i < 2; i++) {
        int row0 = m0 + warp_m * 32 + i * 16 + g;
        #pragma unroll
        for (int j = 0; j < 8; j++) {
            int col = n0 + warp_n * 64 + j * 8 + 2 * t4;
            float cb0 = g_cb[col], cb1 = g_cb[col + 1];
            if (row0 < N) {
                float2 v = make_float2(acc[i][j][0] + cb0, acc[i][j][1] + cb1);
                *(float2*)(g_c + (size_t)row0 * HIDDEN + col) = v;
            }
            if (row0 + 8 < N) {
                float2 v = make_float2(acc[i][j][2] + cb0, acc[i][j][3] + cb1);
                *(float2*)(g_c + (size_t)(row0 + 8) * HIDDEN + col) = v;
            }
        }
    }
}

// ---------------- CSR build ----------------
__global__ void k_zero(int N) {
    int i = blockIdx.x * blockDim.x + threadIdx.x;
    if (i < N) g_counts[i] = 0;
}

__global__ void k_hist(const void* __restrict__ rowp, int E) {
    int e = blockIdx.x * blockDim.x + threadIdx.x;
    if (e >= E) return;
    int r = g_is64 ? (int)((const long long*)rowp)[e] : ((const int*)rowp)[e];
    atomicAdd(&g_counts[r], 1);
}

__global__ void k_scan(int N) {
    __shared__ int sh[1024];
    int tid = threadIdx.x;
    int chunk = (N + 1023) >> 10;
    int lo = tid * chunk;
    int hi = lo + chunk; if (hi > N) hi = N; if (lo > N) lo = N;
    int s = 0;
    for (int i = lo; i < hi; i++) s += g_counts[i];
    sh[tid] = s;
    __syncthreads();
    int v = s;
    for (int o = 1; o < 1024; o <<= 1) {
        int u = (tid >= o) ? sh[tid - o] : 0;
        __syncthreads();
        v += u;
        sh[tid] = v;
        __syncthreads();
    }
    int run = v - s;
    for (int i = lo; i < hi; i++) {
        g_rowstart[i] = run;
        g_cursor[i]   = run;
        run += g_counts[i];
    }
}

__global__ void k_scatter(const void* __restrict__ rowp,
                          const void* __restrict__ colp, int E) {
    int e = blockIdx.x * blockDim.x + threadIdx.x;
    if (e >= E) return;
    int r, c;
    if (g_is64) {
        r = (int)((const long long*)rowp)[e];
        c = (int)((const long long*)colp)[e];
    } else {
        r = ((const int*)rowp)[e];
        c = ((const int*)colp)[e];
    }
    int pos = atomicAdd(&g_cursor[r], 1);
    g_csrcol[pos] = c;
}

// ---------------- fused aggregate + bias + norm + classifier ----------------
__global__ __launch_bounds__(256)
void k_agg(const float* __restrict__ asg_b1, const float* __restrict__ asg_W2,
           const float* __restrict__ asg_b2, const float* __restrict__ bias,
           const float* __restrict__ cls_W, const float* __restrict__ cls_b,
           float* __restrict__ hout, float* __restrict__ logits, int N) {
    __shared__ float sw[8][32][4];
    __shared__ int   sc[8][32];

    int wid  = threadIdx.x >> 5;
    int lane = threadIdx.x & 31;
    int r    = blockIdx.x * 8 + wid;
    if (r >= N) return;

    float b1[4], b2r[4], W2[16];
    #pragma unroll
    for (int k = 0; k < 4; k++) { b1[k] = __ldg(asg_b1 + k); b2r[k] = __ldg(asg_b2 + k); }
    #pragma unroll
    for (int k = 0; k < 16; k++) W2[k] = __ldg(asg_W2 + k);

    float4 pbv = *(const float4*)(g_proj + r * 8 + 4);
    float pb[4] = {pbv.x, pbv.y, pbv.z, pbv.w};

    int start = g_rowstart[r];
    int deg   = g_counts[r];
    int myg   = lane >> 3;

    ull ap0 = 0ull, ap1 = 0ull, ap2 = 0ull, ap3 = 0ull;

    for (int base = 0; base < deg; base += 32) {
        int cnt = deg - base; if (cnt > 32) cnt = 32;
        float w0 = 0.f, w1 = 0.f, w2 = 0.f, w3 = 0.f;
        int   mycol = 0;
        if (lane < cnt) {
            mycol = g_csrcol[start + base + lane];
            float4 pav = __ldg((const float4*)(g_proj + (size_t)mycol * 8));
            float h1[4] = {pav.x + pb[0] + b1[0], pav.y + pb[1] + b1[1],
                           pav.z + pb[2] + b1[2], pav.w + pb[3] + b1[3]};
            float h2[4], mx = -1e30f;
            #pragma unroll
            for (int k = 0; k < 4; k++) {
                float s = b2r[k];
                #pragma unroll
                for (int d = 0; d < 4; d++) s = fmaf(h1[d], W2[k*4+d], s);
                h2[k] = s; mx = fmaxf(mx, s);
            }
            float e0 = __expf(h2[0]-mx), e1 = __expf(h2[1]-mx);
            float e2 = __expf(h2[2]-mx), e3 = __expf(h2[3]-mx);
            float inv = 1.f / (e0+e1+e2+e3);
            w0 = e0*inv; w1 = e1*inv; w2 = e2*inv; w3 = e3*inv;
        }
        sw[wid][lane][0] = w0; sw[wid][lane][1] = w1;
        sw[wid][lane][2] = w2; sw[wid][lane][3] = w3;
        sc[wid][lane] = mycol;
        __syncwarp();

        #pragma unroll 4
        for (int j = 0; j < cnt; j++) {
            int   cj = sc[wid][j];
            float wj = sw[wid][j][myg];
            ull   wj2 = pack2(wj, wj);
            const ulonglong2* cr =
                (const ulonglong2*)(g_c + (size_t)cj * HIDDEN) + lane * 2;
            ulonglong2 v0 = __ldg(cr);
            ulonglong2 v1 = __ldg(cr + 1);
            ffma2(ap0, v0.x, wj2); ffma2(ap1, v0.y, wj2);
            ffma2(ap2, v1.x, wj2); ffma2(ap3, v1.y, wj2);
        }
        __syncwarp();
    }

    float a[8];
    unpack2(ap0, a[0], a[1]); unpack2(ap1, a[2], a[3]);
    unpack2(ap2, a[4], a[5]); unpack2(ap3, a[6], a[7]);

    float4 bb0 = __ldg((const float4*)bias + lane * 2);
    float4 bb1 = __ldg((const float4*)bias + lane * 2 + 1);
    a[0] += bb0.x; a[1] += bb0.y; a[2] += bb0.z; a[3] += bb0.w;
    a[4] += bb1.x; a[5] += bb1.y; a[6] += bb1.z; a[7] += bb1.w;

    float ss = 0.f;
    #pragma unroll
    for (int t = 0; t < 8; t++) ss = fmaf(a[t], a[t], ss);
    #pragma unroll
    for (int o = 1; o < 8; o <<= 1)
        ss += __shfl_xor_sync(0xFFFFFFFFu, ss, o);
    float invn = 1.f / fmaxf(sqrtf(ss), 1e-12f);
    #pragma unroll
    for (int t = 0; t < 8; t++) a[t] *= invn;

    float4* hr = (float4*)(hout + (size_t)r * HIDDEN) + lane * 2;
    hr[0] = make_float4(a[0], a[1], a[2], a[3]);
    hr[1] = make_float4(a[4], a[5], a[6], a[7]);

    float lp[4];
    #pragma unroll
    for (int cc = 0; cc < 4; cc++) {
        const float4* cwp = (const float4*)(cls_W + cc * HIDDEN) + lane * 2;
        float4 c0 = __ldg(cwp), c1 = __ldg(cwp + 1);
        lp[cc] = a[0]*c0.x + a[1]*c0.y + a[2]*c0.z + a[3]*c0.w
               + a[4]*c1.x + a[5]*c1.y + a[6]*c1.z + a[7]*c1.w;
    }
    #pragma unroll
    for (int cc = 0; cc < 4; cc++)
        #pragma unroll
        for (int o = 16; o > 0; o >>= 1)
            lp[cc] += __shfl_xor_sync(0xFFFFFFFFu, lp[cc], o);
    if (lane == 0) {
        #pragma unroll
        for (int cc = 0; cc < 4; cc++)
            logits[(size_t)r * NCLASS + cc] = lp[cc] + __ldg(cls_b + cc);
    }
}

// ---------------- launch ----------------
extern "C" void kernel_launch(void* const* d_in, const int* in_sizes, int n_in,
                              void* d_out, int out_size) {
    const float* x      = (const float*)d_in[0];
    const void*  rowp   = d_in[1];
    const void*  colp   = d_in[2];
    const float* asg_W1 = (const float*)d_in[3];
    const float* asg_b1 = (const float*)d_in[4];
    const float* asg_W2 = (const float*)d_in[5];
    const float* asg_b2 = (const float*)d_in[6];
    const float* lin_W  = (const float*)d_in[7];
    const float* lin_b  = (const float*)d_in[8];
    const float* conv_W = (const float*)d_in[9];
    const float* bias   = (const float*)d_in[10];
    const float* cls_W  = (const float*)d_in[11];
    const float* cls_b  = (const float*)d_in[12];

    int N = in_sizes[0] / NFEAT;
    int E = in_sizes[1];

    float* hout   = (float*)d_out;
    float* logits = hout + (size_t)N * HIDDEN;

    cudaFuncSetAttribute(k_cmma, cudaFuncAttributeMaxDynamicSharedMemorySize,
                         SM_DYN);

    k_detect<<<1, 32>>>((const unsigned int*)rowp, E);
    k_fold<<<HIDDEN, NFEAT>>>(conv_W, lin_W, lin_b);
    k_proj<<<(N + 7) / 8, 256>>>(x, asg_W1, N);
    dim3 gg((N + 127) / 128, HIDDEN / 128);
    k_cmma<<<gg, 256, SM_DYN>>>(N);
    k_zero<<<(N + 255) / 256, 256>>>(N);
    k_hist<<<(E + 255) / 256, 256>>>(rowp, E);
    k_scan<<<1, 1024>>>(N);
    k_scatter<<<(E + 255) / 256, 256>>>(rowp, colp, E);
    k_agg<<<(N + 7) / 8, 256>>>(asg_b1, asg_W2, asg_b2, bias,
                                cls_W, cls_b, hout, logits, N);
}

// round 10
// speedup vs baseline: 2.7942x; 1.2538x over previous
#include <cuda_runtime.h>
#include <cuda_bf16.h>
#include <math.h>
#include <cstdint>

#define NFEAT   256
#define HIDDEN  256
#define PCH     64
#define NCLASS  4
#define MAXN    100000
#define MAXE    1600000

typedef unsigned long long ull;

__device__ __forceinline__ ull pack2(float x, float y) {
    ull r; asm("mov.b64 %0, {%1,%2};" : "=l"(r) : "f"(x), "f"(y)); return r;
}
__device__ __forceinline__ void unpack2(ull v, float& x, float& y) {
    asm("mov.b64 {%0,%1}, %2;" : "=f"(x), "=f"(y) : "l"(v));
}
__device__ __forceinline__ void ffma2(ull& d, ull a, ull b) {
    asm("fma.rn.f32x2 %0, %1, %2, %0;" : "+l"(d) : "l"(a), "l"(b));
}
__device__ __forceinline__ uint32_t smem_u32(const void* p) {
    uint32_t a;
    asm("{ .reg .u64 t; cvta.to.shared.u64 t, %1; cvt.u32.u64 %0, t; }"
        : "=r"(a) : "l"(p));
    return a;
}
__device__ __forceinline__ void ldsm4(uint32_t addr, uint32_t& r0, uint32_t& r1,
                                      uint32_t& r2, uint32_t& r3) {
    asm volatile("ldmatrix.sync.aligned.m8n8.x4.shared.b16 {%0,%1,%2,%3}, [%4];"
                 : "=r"(r0), "=r"(r1), "=r"(r2), "=r"(r3) : "r"(addr));
}
__device__ __forceinline__ void mma16816(float* c, uint32_t a0, uint32_t a1,
                                         uint32_t a2, uint32_t a3,
                                         uint32_t b0, uint32_t b1) {
    asm volatile(
        "mma.sync.aligned.m16n8k16.row.col.f32.bf16.bf16.f32 "
        "{%0,%1,%2,%3}, {%4,%5,%6,%7}, {%8,%9}, {%0,%1,%2,%3};"
        : "+f"(c[0]), "+f"(c[1]), "+f"(c[2]), "+f"(c[3])
        : "r"(a0), "r"(a1), "r"(a2), "r"(a3), "r"(b0), "r"(b1));
}
__device__ __forceinline__ void cp16z(uint32_t dst, const void* src, int inb) {
    int sz = inb ? 16 : 0;
    asm volatile("cp.async.cg.shared.global [%0], [%1], 16, %2;"
                 :: "r"(dst), "l"(src), "r"(sz));
}
__device__ __forceinline__ void cp16(uint32_t dst, const void* src) {
    asm volatile("cp.async.cg.shared.global [%0], [%1], 16;"
                 :: "r"(dst), "l"(src));
}

// ---------------- device scratch ----------------
__device__ int   g_is64;
__device__ float g_cb[HIDDEN];
__device__ float g_proj[MAXN * 8];
__device__ float g_c[(size_t)MAXN * HIDDEN];
__device__ __nv_bfloat16 g_xhi[(size_t)MAXN * NFEAT];
__device__ __nv_bfloat16 g_xlo[(size_t)MAXN * NFEAT];
__device__ __nv_bfloat16 g_cwhi[HIDDEN * NFEAT];
__device__ __nv_bfloat16 g_cwlo[HIDDEN * NFEAT];
__device__ int   g_counts[MAXN];
__device__ int   g_rowstart[MAXN];
__device__ int   g_cursor[MAXN];
__device__ int   g_csrcol[MAXE];
__device__ int   g_bsum[512];
__device__ int   g_boff[512];

// ---------------- index width sniffing ----------------
__global__ void k_detect(const unsigned int* __restrict__ rowp, int E) {
    if (threadIdx.x == 0 && blockIdx.x == 0) {
        int n = E < 64 ? E : 64;
        int all_hi_zero = 1;
        for (int i = 0; i < n; i++)
            if (rowp[2 * i + 1] != 0u) { all_hi_zero = 0; break; }
        g_is64 = all_hi_zero;
    }
}

// ---------------- fold conv into lin, output bf16 hi/lo ----------------
__global__ void k_fold(const float* __restrict__ conv_W,
                       const float* __restrict__ lin_W,
                       const float* __restrict__ lin_b) {
    int t = blockIdx.x, f = threadIdx.x;
    int k = t >> 6, q = t & 63;
    const float* cw = conv_W + (k * PCH + q) * PCH;
    const float* lw = lin_W + (size_t)k * PCH * NFEAT;
    float s = 0.f;
    #pragma unroll 8
    for (int p = 0; p < PCH; p++) s = fmaf(cw[p], lw[p * NFEAT + f], s);
    __nv_bfloat16 hi = __float2bfloat16(s);
    g_cwhi[t * NFEAT + f] = hi;
    g_cwlo[t * NFEAT + f] = __float2bfloat16(s - __bfloat162float(hi));
    if (f == 0) {
        const float* lb = lin_b + k * PCH;
        float b = 0.f;
        for (int p = 0; p < PCH; p++) b = fmaf(cw[p], lb[p], b);
        g_cb[t] = b;
    }
}

// ---------------- projections + x split (single x read) ----------------
__global__ void k_proj(const float* __restrict__ x,
                       const float* __restrict__ asg_W1, int N) {
    int warp = (blockIdx.x * blockDim.x + threadIdx.x) >> 5;
    int lane = threadIdx.x & 31;
    if (warp >= N) return;
    const float* xr = x + (size_t)warp * NFEAT;
    float pa[4] = {0,0,0,0}, pb[4] = {0,0,0,0};
    #pragma unroll
    for (int t = 0; t < 8; t++) {
        int f = lane + 32 * t;
        float xv = xr[f];
        __nv_bfloat16 h = __float2bfloat16(xv);
        g_xhi[(size_t)warp * NFEAT + f] = h;
        g_xlo[(size_t)warp * NFEAT + f] =
            __float2bfloat16(xv - __bfloat162float(h));
        #pragma unroll
        for (int c = 0; c < 4; c++) {
            pa[c] = fmaf(xv, asg_W1[c * 512 + f], pa[c]);
            pb[c] = fmaf(xv, asg_W1[c * 512 + 256 + f], pb[c]);
        }
    }
    #pragma unroll
    for (int c = 0; c < 4; c++)
        #pragma unroll
        for (int o = 16; o > 0; o >>= 1) {
            pa[c] += __shfl_xor_sync(0xFFFFFFFFu, pa[c], o);
            pb[c] += __shfl_xor_sync(0xFFFFFFFFu, pb[c], o);
        }
    if (lane == 0) {
        #pragma unroll
        for (int c = 0; c < 4; c++) {
            g_proj[warp * 8 + c]     = pa[c];
            g_proj[warp * 8 + 4 + c] = pb[c];
        }
    }
}

// ---------------- c = X @ CW^T + cb  via mma.sync bf16 split ----------------
#define CHK 32
#define PITCH 80
#define T_AH 0
#define T_AL (128 * PITCH)
#define T_BH (2 * 128 * PITCH)
#define T_BL (3 * 128 * PITCH)
#define STAGE_BYTES (4 * 128 * PITCH)
#define SM_DYN (2 * STAGE_BYTES)
#define NCHUNK (NFEAT / CHK)

__global__ __launch_bounds__(256, 2)
void k_cmma(int N) {
    extern __shared__ __align__(16) char sm[];
    uint32_t sb = smem_u32(sm);
    int tid  = threadIdx.x;
    int wid  = tid >> 5;
    int lane = tid & 31;
    int m0 = blockIdx.x * 128;
    int n0 = blockIdx.y * 128;
    int warp_m = wid >> 1;
    int warp_n = wid & 1;

    float acc[2][8][4];
    #pragma unroll
    for (int i = 0; i < 2; i++)
        #pragma unroll
        for (int j = 0; j < 8; j++)
            #pragma unroll
            for (int q = 0; q < 4; q++) acc[i][j][q] = 0.f;

    int a_row = warp_m * 32 + (lane & 15);
    int a_col = (lane >> 4) << 3;
    uint32_t aoff = (uint32_t)(a_row * PITCH + a_col * 2);
    int b_row_base = warp_n * 64 + ((lane >> 4) << 3) + (lane & 7);
    int b_col = ((lane >> 3) & 1) << 3;
    uint32_t boff = (uint32_t)(b_row_base * PITCH + b_col * 2);

    int lrow = tid >> 2;
    int lseg = tid & 3;

    auto load_stage = [&](int s, int k0) {
        uint32_t sgb = sb + (uint32_t)(s * STAGE_BYTES);
        #pragma unroll
        for (int ps = 0; ps < 2; ps++) {
            int r = lrow + ps * 64;
            uint32_t dst = sgb + (uint32_t)(r * PITCH + lseg * 16);
            int gm = m0 + r;
            int inb = gm < N;
            const __nv_bfloat16* ah = g_xhi + (size_t)(inb ? gm : 0) * NFEAT + k0 + lseg * 8;
            const __nv_bfloat16* al = g_xlo + (size_t)(inb ? gm : 0) * NFEAT + k0 + lseg * 8;
            cp16z(dst + T_AH, ah, inb);
            cp16z(dst + T_AL, al, inb);
            int gn = n0 + r;
            cp16(dst + T_BH, g_cwhi + (size_t)gn * NFEAT + k0 + lseg * 8);
            cp16(dst + T_BL, g_cwlo + (size_t)gn * NFEAT + k0 + lseg * 8);
        }
        asm volatile("cp.async.commit_group;");
    };

    load_stage(0, 0);

    #pragma unroll 1
    for (int chunk = 0; chunk < NCHUNK; chunk++) {
        int s = chunk & 1;
        asm volatile("cp.async.wait_group 0;" ::: "memory");
        __syncthreads();
        if (chunk + 1 < NCHUNK) load_stage(s ^ 1, (chunk + 1) * CHK);

        uint32_t sgb = sb + (uint32_t)(s * STAGE_BYTES);
        #pragma unroll
        for (int ka = 0; ka < CHK / 16; ka++) {
            uint32_t kb = (uint32_t)(ka * 16 * 2);
            uint32_t ah[2][4], al[2][4];
            #pragma unroll
            for (int i = 0; i < 2; i++) {
                uint32_t aa = sgb + aoff + kb + (uint32_t)(i * 16 * PITCH);
                ldsm4(aa + T_AH, ah[i][0], ah[i][1], ah[i][2], ah[i][3]);
                ldsm4(aa + T_AL, al[i][0], al[i][1], al[i][2], al[i][3]);
            }
            #pragma unroll
            for (int jp = 0; jp < 4; jp++) {
                uint32_t ba = sgb + boff + kb + (uint32_t)(jp * 16 * PITCH);
                uint32_t bh[4], bl[4];
                ldsm4(ba + T_BH, bh[0], bh[1], bh[2], bh[3]);
                ldsm4(ba + T_BL, bl[0], bl[1], bl[2], bl[3]);
                #pragma unroll
                for (int i = 0; i < 2; i++) {
                    float* c0 = acc[i][2 * jp];
                    float* c1 = acc[i][2 * jp + 1];
                    mma16816(c0, ah[i][0], ah[i][1], ah[i][2], ah[i][3], bh[0], bh[1]);
                    mma16816(c0, al[i][0], al[i][1], al[i][2], al[i][3], bh[0], bh[1]);
                    mma16816(c0, ah[i][0], ah[i][1], ah[i][2], ah[i][3], bl[0], bl[1]);
                    mma16816(c1, ah[i][0], ah[i][1], ah[i][2], ah[i][3], bh[2], bh[3]);
                    mma16816(c1, al[i][0], al[i][1], al[i][2], al[i][3], bh[2], bh[3]);
                    mma16816(c1, ah[i][0], ah[i][1], ah[i][2], ah[i][3], bl[2], bl[3]);
                }
            }
        }
        __syncthreads();
    }

    int g = lane >> 2, t4 = lane & 3;
    #pragma unroll
    for (int i = 0; i < 2; i++) {
        int row0 = m0 + warp_m * 32 + i * 16 + g;
        #pragma unroll
        for (int j = 0; j < 8; j++) {
            int col = n0 + warp_n * 64 + j * 8 + 2 * t4;
            float cb0 = g_cb[col], cb1 = g_cb[col + 1];
            if (row0 < N) {
                float2 v = make_float2(acc[i][j][0] + cb0, acc[i][j][1] + cb1);
                *(float2*)(g_c + (size_t)row0 * HIDDEN + col) = v;
            }
            if (row0 + 8 < N) {
                float2 v = make_float2(acc[i][j][2] + cb0, acc[i][j][3] + cb1);
                *(float2*)(g_c + (size_t)(row0 + 8) * HIDDEN + col) = v;
            }
        }
    }
}

// ---------------- CSR build ----------------
__global__ void k_zero(int N) {
    int i = blockIdx.x * blockDim.x + threadIdx.x;
    if (i < N) g_counts[i] = 0;
}

__global__ void k_hist(const void* __restrict__ rowp, int E) {
    int e = blockIdx.x * blockDim.x + threadIdx.x;
    if (e >= E) return;
    int r = g_is64 ? (int)((const long long*)rowp)[e] : ((const int*)rowp)[e];
    atomicAdd(&g_counts[r], 1);
}

// coalesced 3-phase scan
__global__ void k_bsum(int N) {
    __shared__ int sh[256];
    int t = threadIdx.x;
    int i = blockIdx.x * 256 + t;
    sh[t] = (i < N) ? g_counts[i] : 0;
    __syncthreads();
    #pragma unroll
    for (int o = 128; o > 0; o >>= 1) {
        if (t < o) sh[t] += sh[t + o];
        __syncthreads();
    }
    if (t == 0) g_bsum[blockIdx.x] = sh[0];
}

__global__ void k_bscan(int nb) {
    __shared__ int sh[512];
    int t = threadIdx.x;
    int v = (t < nb) ? g_bsum[t] : 0;
    sh[t] = v;
    __syncthreads();
    int acc = v;
    #pragma unroll
    for (int o = 1; o < 512; o <<= 1) {
        int u = (t >= o) ? sh[t - o] : 0;
        __syncthreads();
        acc += u;
        sh[t] = acc;
        __syncthreads();
    }
    if (t < nb) g_boff[t] = acc - v;   // exclusive
}

__global__ void k_rows(int N) {
    __shared__ int sh[256];
    int t = threadIdx.x;
    int i = blockIdx.x * 256 + t;
    int v = (i < N) ? g_counts[i] : 0;
    sh[t] = v;
    __syncthreads();
    int acc = v;
    #pragma unroll
    for (int o = 1; o < 256; o <<= 1) {
        int u = (t >= o) ? sh[t - o] : 0;
        __syncthreads();
        acc += u;
        sh[t] = acc;
        __syncthreads();
    }
    if (i < N) {
        int start = g_boff[blockIdx.x] + acc - v;
        g_rowstart[i] = start;
        g_cursor[i]   = start;
    }
}

__global__ void k_scatter(const void* __restrict__ rowp,
                          const void* __restrict__ colp, int E) {
    int e = blockIdx.x * blockDim.x + threadIdx.x;
    if (e >= E) return;
    int r, c;
    if (g_is64) {
        r = (int)((const long long*)rowp)[e];
        c = (int)((const long long*)colp)[e];
    } else {
        r = ((const int*)rowp)[e];
        c = ((const int*)colp)[e];
    }
    int pos = atomicAdd(&g_cursor[r], 1);
    g_csrcol[pos] = c;
}

// ---------------- fused aggregate + bias + norm + classifier ----------------
__global__ __launch_bounds__(256)
void k_agg(const float* __restrict__ asg_b1, const float* __restrict__ asg_W2,
           const float* __restrict__ asg_b2, const float* __restrict__ bias,
           const float* __restrict__ cls_W, const float* __restrict__ cls_b,
           float* __restrict__ hout, float* __restrict__ logits, int N) {
    __shared__ float sw[8][32][4];
    __shared__ int   sc[8][32];

    int wid  = threadIdx.x >> 5;
    int lane = threadIdx.x & 31;
    int r    = blockIdx.x * 8 + wid;
    if (r >= N) return;

    float b1[4], b2r[4], W2[16];
    #pragma unroll
    for (int k = 0; k < 4; k++) { b1[k] = __ldg(asg_b1 + k); b2r[k] = __ldg(asg_b2 + k); }
    #pragma unroll
    for (int k = 0; k < 16; k++) W2[k] = __ldg(asg_W2 + k);

    float4 pbv = *(const float4*)(g_proj + r * 8 + 4);
    float pb[4] = {pbv.x, pbv.y, pbv.z, pbv.w};

    int start = g_rowstart[r];
    int deg   = g_counts[r];
    int myg   = lane >> 3;

    ull ap0 = 0ull, ap1 = 0ull, ap2 = 0ull, ap3 = 0ull;

    for (int base = 0; base < deg; base += 32) {
        int cnt = deg - base; if (cnt > 32) cnt = 32;
        float w0 = 0.f, w1 = 0.f, w2 = 0.f, w3 = 0.f;
        int   mycol = 0;
        if (lane < cnt) {
            mycol = g_csrcol[start + base + lane];
            float4 pav = __ldg((const float4*)(g_proj + (size_t)mycol * 8));
            float h1[4] = {pav.x + pb[0] + b1[0], pav.y + pb[1] + b1[1],
                           pav.z + pb[2] + b1[2], pav.w + pb[3] + b1[3]};
            float h2[4], mx = -1e30f;
            #pragma unroll
            for (int k = 0; k < 4; k++) {
                float s = b2r[k];
                #pragma unroll
                for (int d = 0; d < 4; d++) s = fmaf(h1[d], W2[k*4+d], s);
                h2[k] = s; mx = fmaxf(mx, s);
            }
            float e0 = __expf(h2[0]-mx), e1 = __expf(h2[1]-mx);
            float e2 = __expf(h2[2]-mx), e3 = __expf(h2[3]-mx);
            float inv = 1.f / (e0+e1+e2+e3);
            w0 = e0*inv; w1 = e1*inv; w2 = e2*inv; w3 = e3*inv;
        }
        sw[wid][lane][0] = w0; sw[wid][lane][1] = w1;
        sw[wid][lane][2] = w2; sw[wid][lane][3] = w3;
        sc[wid][lane] = mycol;
        __syncwarp();

        #pragma unroll 8
        for (int j = 0; j < cnt; j++) {
            int   cj = sc[wid][j];
            float wj = sw[wid][j][myg];
            ull   wj2 = pack2(wj, wj);
            const ulonglong2* cr =
                (const ulonglong2*)(g_c + (size_t)cj * HIDDEN) + lane * 2;
            ulonglong2 v0 = __ldg(cr);
            ulonglong2 v1 = __ldg(cr + 1);
            ffma2(ap0, v0.x, wj2); ffma2(ap1, v0.y, wj2);
            ffma2(ap2, v1.x, wj2); ffma2(ap3, v1.y, wj2);
        }
        __syncwarp();
    }

    float a[8];
    unpack2(ap0, a[0], a[1]); unpack2(ap1, a[2], a[3]);
    unpack2(ap2, a[4], a[5]); unpack2(ap3, a[6], a[7]);

    float4 bb0 = __ldg((const float4*)bias + lane * 2);
    float4 bb1 = __ldg((const float4*)bias + lane * 2 + 1);
    a[0] += bb0.x; a[1] += bb0.y; a[2] += bb0.z; a[3] += bb0.w;
    a[4] += bb1.x; a[5] += bb1.y; a[6] += bb1.z; a[7] += bb1.w;

    float ss = 0.f;
    #pragma unroll
    for (int t = 0; t < 8; t++) ss = fmaf(a[t], a[t], ss);
    #pragma unroll
    for (int o = 1; o < 8; o <<= 1)
        ss += __shfl_xor_sync(0xFFFFFFFFu, ss, o);
    float invn = 1.f / fmaxf(sqrtf(ss), 1e-12f);
    #pragma unroll
    for (int t = 0; t < 8; t++) a[t] *= invn;

    float4* hr = (float4*)(hout + (size_t)r * HIDDEN) + lane * 2;
    hr[0] = make_float4(a[0], a[1], a[2], a[3]);
    hr[1] = make_float4(a[4], a[5], a[6], a[7]);

    float lp[4];
    #pragma unroll
    for (int cc = 0; cc < 4; cc++) {
        const float4* cwp = (const float4*)(cls_W + cc * HIDDEN) + lane * 2;
        float4 c0 = __ldg(cwp), c1 = __ldg(cwp + 1);
        lp[cc] = a[0]*c0.x + a[1]*c0.y + a[2]*c0.z + a[3]*c0.w
               + a[4]*c1.x + a[5]*c1.y + a[6]*c1.z + a[7]*c1.w;
    }
    #pragma unroll
    for (int cc = 0; cc < 4; cc++)
        #pragma unroll
        for (int o = 16; o > 0; o >>= 1)
            lp[cc] += __shfl_xor_sync(0xFFFFFFFFu, lp[cc], o);
    if (lane == 0) {
        #pragma unroll
        for (int cc = 0; cc < 4; cc++)
            logits[(size_t)r * NCLASS + cc] = lp[cc] + __ldg(cls_b + cc);
    }
}

// ---------------- launch ----------------
extern "C" void kernel_launch(void* const* d_in, const int* in_sizes, int n_in,
                              void* d_out, int out_size) {
    const float* x      = (const float*)d_in[0];
    const void*  rowp   = d_in[1];
    const void*  colp   = d_in[2];
    const float* asg_W1 = (const float*)d_in[3];
    const float* asg_b1 = (const float*)d_in[4];
    const float* asg_W2 = (const float*)d_in[5];
    const float* asg_b2 = (const float*)d_in[6];
    const float* lin_W  = (const float*)d_in[7];
    const float* lin_b  = (const float*)d_in[8];
    const float* conv_W = (const float*)d_in[9];
    const float* bias   = (const float*)d_in[10];
    const float* cls_W  = (const float*)d_in[11];
    const float* cls_b  = (const float*)d_in[12];

    int N = in_sizes[0] / NFEAT;
    int E = in_sizes[1];
    int nb = (N + 255) / 256;

    float* hout   = (float*)d_out;
    float* logits = hout + (size_t)N * HIDDEN;

    cudaFuncSetAttribute(k_cmma, cudaFuncAttributeMaxDynamicSharedMemorySize,
                         SM_DYN);

    k_detect<<<1, 32>>>((const unsigned int*)rowp, E);
    k_fold<<<HIDDEN, NFEAT>>>(conv_W, lin_W, lin_b);
    k_proj<<<(N + 7) / 8, 256>>>(x, asg_W1, N);
    dim3 gg((N + 127) / 128, HIDDEN / 128);
    k_cmma<<<gg, 256, SM_DYN>>>(N);
    k_zero<<<(N + 255) / 256, 256>>>(N);
    k_hist<<<(E + 255) / 256, 256>>>(rowp, E);
    k_bsum<<<nb, 256>>>(N);
    k_bscan<<<1, 512>>>(nb);
    k_rows<<<nb, 256>>>(N);
    k_scatter<<<(E + 255) / 256, 256>>>(rowp, colp, E);
    k_agg<<<(N + 7) / 8, 256>>>(asg_b1, asg_W2, asg_b2, bias,
                                cls_W, cls_b, hout, logits, N);
}